// round 9
// baseline (speedup 1.0000x reference)
#include <cuda_runtime.h>
#include <cuda_bf16.h>
#include <cstdint>
#include <math.h>

#define NN 2048
#define DD 768
#define HH 12
#define YY 64

#define NQT 32                 // q-tiles per head (qtile = 64 rows)
#define NGRP (HH * NQT)        // 384 (h, qt) groups
#define KSPLIT 2               // K-range halves per group

// ---------------------------------------------------------------------------
// Scratch (__device__ globals; no allocation allowed)
// ---------------------------------------------------------------------------
__device__ __nv_bfloat16 g_gb [NN * DD];       // g in bf16
__device__ __nv_bfloat16 g_Wqb[HH * YY * DD];  // Wq in bf16
__device__ __nv_bfloat16 g_Wkb[HH * YY * DD];  // Wk in bf16
__device__ __nv_bfloat16 g_Q[HH * NN * YY];    // [h][n][y], pre-scaled by beta
__device__ __nv_bfloat16 g_K[HH * NN * YY];    // [h][n][y]
__device__ float2 g_ml[NGRP * KSPLIT * 64];    // per-row (m,l) per half
__device__ float g_partial[NGRP];              // per-group LSE row sums
__device__ unsigned int g_ticket2[NGRP];       // per-group pair election
__device__ unsigned int g_ticket;              // global last-group election

// ---------------------------------------------------------------------------
// Helpers (standard sm_80+ features: ldmatrix / mma.sync / cp.async)
// ---------------------------------------------------------------------------
__device__ __forceinline__ uint32_t smem_u32(const void* p) {
    uint32_t a;
    asm("{ .reg .u64 t; cvta.to.shared.u64 t, %1; cvt.u32.u64 %0, t; }" : "=r"(a) : "l"(p));
    return a;
}

__device__ __forceinline__ void cpa16(uint32_t dst, const void* src) {
    asm volatile("cp.async.cg.shared.global [%0], [%1], 16;" :: "r"(dst), "l"(src));
}
#define CP_COMMIT() asm volatile("cp.async.commit_group;" ::: "memory")
#define CP_WAIT(n)  asm volatile("cp.async.wait_group %0;" :: "n"(n) : "memory")

__device__ __forceinline__ void ldsm4(uint32_t& r0, uint32_t& r1, uint32_t& r2, uint32_t& r3,
                                      uint32_t addr) {
    asm volatile("ldmatrix.sync.aligned.m8n8.x4.shared.b16 {%0,%1,%2,%3}, [%4];"
                 : "=r"(r0), "=r"(r1), "=r"(r2), "=r"(r3) : "r"(addr));
}

__device__ __forceinline__ void mma16816(float* c, const uint32_t* a, uint32_t b0, uint32_t b1) {
    asm volatile(
        "mma.sync.aligned.m16n8k16.row.col.f32.bf16.bf16.f32 "
        "{%0,%1,%2,%3}, {%4,%5,%6,%7}, {%8,%9}, {%0,%1,%2,%3};"
        : "+f"(c[0]), "+f"(c[1]), "+f"(c[2]), "+f"(c[3])
        : "r"(a[0]), "r"(a[1]), "r"(a[2]), "r"(a[3]), "r"(b0), "r"(b1));
}

__device__ __forceinline__ uint32_t bf16x2(float hi, float lo) {
    uint32_t r;
    asm("cvt.rn.bf16x2.f32 %0, %1, %2;" : "=r"(r) : "f"(hi), "f"(lo));
    return r;
}

// ---------------------------------------------------------------------------
// Convert f32 inputs -> bf16 globals; reset tickets for this launch.
// ---------------------------------------------------------------------------
#define NG8 (NN * DD / 8)          // 196608
#define NW8 (HH * YY * DD / 8)     // 73728

__global__ void __launch_bounds__(256) conv_kernel(const float* __restrict__ g,
                                                   const float* __restrict__ wq,
                                                   const float* __restrict__ wk)
{
    int i = blockIdx.x * 256 + threadIdx.x;
    if (i == 0) g_ticket = 0;
    if (i < NGRP) g_ticket2[i] = 0;
    const float* src;
    __nv_bfloat16* dst;
    int j;
    if (i < NG8)                { src = g;  dst = g_gb;  j = i; }
    else if (i < NG8 + NW8)     { src = wq; dst = g_Wqb; j = i - NG8; }
    else if (i < NG8 + 2 * NW8) { src = wk; dst = g_Wkb; j = i - NG8 - NW8; }
    else return;
    float4 v0 = *reinterpret_cast<const float4*>(src + (size_t)j * 8);
    float4 v1 = *reinterpret_cast<const float4*>(src + (size_t)j * 8 + 4);
    uint4 o;
    o.x = bf16x2(v0.y, v0.x);
    o.y = bf16x2(v0.w, v0.z);
    o.z = bf16x2(v1.y, v1.x);
    o.w = bf16x2(v1.w, v1.z);
    *reinterpret_cast<uint4*>(dst + (size_t)j * 8) = o;
}

// ---------------------------------------------------------------------------
// Projection: Out[c][n] for c = h*64+y.  Out = g . W^T.
// CTA tile 64n x 128c, 128 threads (4 warps: 2m x 2n, warp tile 32x64).
// 3-stage cp.async pipeline, ONE __syncthreads per k-chunk.
// grid (6, 32, 2) = 384 CTAs. Dynamic smem: 3*15360 = 46080 B (< 48KB).
// ---------------------------------------------------------------------------
#define PROWB 80
#define PA_TILE (64 * PROWB)                // 5120 B
#define PB_TILE (128 * PROWB)               // 10240 B
#define P_STAGE (PA_TILE + PB_TILE)         // 15360 B
#define P_SMEM (3 * P_STAGE)                // 46080 B

__global__ void __launch_bounds__(128) proj_kernel()
{
    extern __shared__ char sm[];
    const uint32_t sb = smem_u32(sm);
    const int tid = threadIdx.x, lane = tid & 31, wid = tid >> 5;
    const int wm = wid & 1, wn = wid >> 1;
    const int c0 = blockIdx.x * 128, n0 = blockIdx.y * 64;
    const __nv_bfloat16* __restrict__ A = g_gb;
    const __nv_bfloat16* __restrict__ B = blockIdx.z ? g_Wkb : g_Wqb;
    __nv_bfloat16* __restrict__ Out = blockIdx.z ? g_K : g_Q;
    const float scale = blockIdx.z ? 1.0f : 0.125f;

    auto load_chunk = [&](int ch, int st) {
        const int d0 = ch * 32;
        const uint32_t abuf = sb + st * P_STAGE;
        const uint32_t bbuf = abuf + PA_TILE;
        #pragma unroll
        for (int i = 0; i < 2; i++) {
            int gi = tid + i * 128;
            int r = gi >> 2, c = gi & 3;
            cpa16(abuf + r * PROWB + c * 16, A + (size_t)(n0 + r) * DD + d0 + c * 8);
        }
        #pragma unroll
        for (int i = 0; i < 4; i++) {
            int gi = tid + i * 128;
            int r = gi >> 2, c = gi & 3;
            cpa16(bbuf + r * PROWB + c * 16, B + (size_t)(c0 + r) * DD + d0 + c * 8);
        }
    };

    float acc[2][8][4];
    #pragma unroll
    for (int mt = 0; mt < 2; mt++)
        #pragma unroll
        for (int nt = 0; nt < 8; nt++)
            #pragma unroll
            for (int k = 0; k < 4; k++) acc[mt][nt][k] = 0.f;

    const int lr = lane & 7;
    const uint32_t aoff = (uint32_t)((wm * 32 + lr + ((lane >> 3) & 1) * 8) * PROWB
                                     + ((lane >> 4) & 1) * 16);
    const uint32_t boff = (uint32_t)((wn * 64 + lr + ((lane >> 4) & 1) * 8) * PROWB
                                     + ((lane >> 3) & 1) * 16);

    load_chunk(0, 0); CP_COMMIT();
    load_chunk(1, 1); CP_COMMIT();

    int rst = 0, wst = 2;
    for (int ch = 0; ch < 24; ch++) {
        if (ch < 23) CP_WAIT(1); else CP_WAIT(0);
        __syncthreads();

        const uint32_t stage = sb + rst * P_STAGE;
        const uint32_t abase = stage + aoff;
        const uint32_t bbase = stage + PA_TILE + boff;
        #pragma unroll
        for (int ks = 0; ks < 2; ks++) {
            uint32_t a0[4], a1[4];
            ldsm4(a0[0], a0[1], a0[2], a0[3], abase + ks * 32);
            ldsm4(a1[0], a1[1], a1[2], a1[3], abase + 16 * PROWB + ks * 32);
            #pragma unroll
            for (int ntp = 0; ntp < 4; ntp++) {
                uint32_t b0, b1, b2, b3;
                ldsm4(b0, b1, b2, b3, bbase + ntp * 16 * PROWB + ks * 32);
                mma16816(acc[0][2 * ntp],     a0, b0, b1);
                mma16816(acc[1][2 * ntp],     a1, b0, b1);
                mma16816(acc[0][2 * ntp + 1], a0, b2, b3);
                mma16816(acc[1][2 * ntp + 1], a1, b2, b3);
            }
        }
        if (ch < 22) { load_chunk(ch + 2, wst); CP_COMMIT(); }
        rst = (rst == 2) ? 0 : rst + 1;
        wst = (wst == 2) ? 0 : wst + 1;
    }

    const int h = (c0 >> 6) + wn;
    const int rbase = n0 + wm * 32 + (lane >> 2);
    #pragma unroll
    for (int mt = 0; mt < 2; mt++) {
        #pragma unroll
        for (int nt = 0; nt < 8; nt++) {
            const int y = nt * 8 + (lane & 3) * 2;
            const int n1 = rbase + mt * 16;
            uint32_t p0 = bf16x2(acc[mt][nt][1] * scale, acc[mt][nt][0] * scale);
            uint32_t p1 = bf16x2(acc[mt][nt][3] * scale, acc[mt][nt][2] * scale);
            *reinterpret_cast<uint32_t*>(&Out[((size_t)h * NN + n1) * YY + y])     = p0;
            *reinterpret_cast<uint32_t*>(&Out[((size_t)h * NN + n1 + 8) * YY + y]) = p1;
        }
    }
}

// ---------------------------------------------------------------------------
// Fused scores + LSE, split-K. CTA per (qtile 64, head, K-half).
// 4 warps retiled 2q x 2k: warp = 32 q-rows x 64 k-cols; each B ldsm feeds
// 4 MMAs (B-LDSM traffic halved vs 1q x 4 layout). Cross-k-warp (m,l) merge
// via smem. grid (32, 12, 2) = 768 CTAs of 128 threads.
// ---------------------------------------------------------------------------
#define ROWB 144
#define S_TILE (128 * ROWB)                 // 18432 B
#define S_RED  (2 * S_TILE)
#define S_SMEM (S_RED + 1024)               // 37888 B

__global__ void __launch_bounds__(128) scores_kernel(float* __restrict__ out)
{
    extern __shared__ char sm[];
    const uint32_t sb = smem_u32(sm);
    const int tid = threadIdx.x, lane = tid & 31, wid = tid >> 5;
    const int wq = wid & 1, wk = wid >> 1;
    const int h = blockIdx.y, qt = blockIdx.x, half = blockIdx.z;
    const int grp = h * NQT + qt;

    const __nv_bfloat16* __restrict__ Qsrc = g_Q + ((size_t)h * NN + qt * 64) * YY;
    const __nv_bfloat16* __restrict__ Ksrc = g_K + (size_t)h * NN * YY
                                           + (size_t)half * (NN / 2) * YY;

    auto load_q = [&]() {
        #pragma unroll
        for (int i = 0; i < 4; i++) {
            int gi = tid + i * 128;
            int r = gi >> 3, c = gi & 7;
            cpa16(sb + r * ROWB + c * 16, Qsrc + (size_t)r * YY + c * 8);
        }
    };
    auto load_k = [&](int ch) {
        const int k0 = ch * 128;
        const uint32_t buf = sb + (ch & 1) * S_TILE;
        #pragma unroll
        for (int i = 0; i < 8; i++) {
            int gi = tid + i * 128;
            int r = gi >> 3, c = gi & 7;
            cpa16(buf + r * ROWB + c * 16, Ksrc + (size_t)(k0 + r) * YY + c * 8);
        }
    };

    const int lr = lane & 7;
    const uint32_t boff = (uint32_t)((wk * 64 + lr + ((lane >> 4) & 1) * 8) * ROWB
                                     + ((lane >> 3) & 1) * 16);

    // Stage Q through buffer 0, pull fragments into registers (2 m-tiles).
    load_q(); CP_COMMIT(); CP_WAIT(0);
    __syncthreads();
    uint32_t aR[2][4][4];
    #pragma unroll
    for (int mt = 0; mt < 2; mt++) {
        const uint32_t aoff = (uint32_t)((wq * 32 + mt * 16 + lr + ((lane >> 3) & 1) * 8) * ROWB
                                         + ((lane >> 4) & 1) * 16);
        #pragma unroll
        for (int ks = 0; ks < 4; ks++)
            ldsm4(aR[mt][ks][0], aR[mt][ks][1], aR[mt][ks][2], aR[mt][ks][3],
                  sb + aoff + ks * 32);
    }
    __syncthreads();

    load_k(0); CP_COMMIT();

    // 4 row-states: s = mt*2+rb; row = wq*32 + mt*16 + rb*8 + (lane>>2)
    float m[4] = {-INFINITY, -INFINITY, -INFINITY, -INFINITY};
    float l[4] = {0.f, 0.f, 0.f, 0.f};

    auto upd = [](float v, float& mm, float& ll) {
        if (v > mm) { ll = ll * __expf(mm - v) + 1.0f; mm = v; }
        else if (v > mm - 16.0f) { ll += __expf(v - mm); }
    };

    for (int ch = 0; ch < 8; ch++) {
        if (ch < 7) { load_k(ch + 1); CP_COMMIT(); CP_WAIT(1); }
        else CP_WAIT(0);
        __syncthreads();

        const uint32_t bbase = sb + (ch & 1) * S_TILE + boff;
        #pragma unroll
        for (int ntp = 0; ntp < 4; ntp++) {
            float acc0[8], acc1[8];
            #pragma unroll
            for (int j = 0; j < 8; j++) { acc0[j] = 0.f; acc1[j] = 0.f; }
            #pragma unroll
            for (int ks = 0; ks < 4; ks++) {
                uint32_t b0, b1, b2, b3;
                ldsm4(b0, b1, b2, b3, bbase + ntp * 16 * ROWB + ks * 32);
                mma16816(acc0,     aR[0][ks], b0, b1);
                mma16816(acc0 + 4, aR[0][ks], b2, b3);
                mma16816(acc1,     aR[1][ks], b0, b1);
                mma16816(acc1 + 4, aR[1][ks], b2, b3);
            }
            float c0a = fmaxf(fmaxf(acc0[0], acc0[1]), fmaxf(acc0[4], acc0[5]));
            float c0b = fmaxf(fmaxf(acc0[2], acc0[3]), fmaxf(acc0[6], acc0[7]));
            float c1a = fmaxf(fmaxf(acc1[0], acc1[1]), fmaxf(acc1[4], acc1[5]));
            float c1b = fmaxf(fmaxf(acc1[2], acc1[3]), fmaxf(acc1[6], acc1[7]));
            if (c0a > m[0] - 16.0f) {
                upd(acc0[0], m[0], l[0]); upd(acc0[1], m[0], l[0]);
                upd(acc0[4], m[0], l[0]); upd(acc0[5], m[0], l[0]);
            }
            if (c0b > m[1] - 16.0f) {
                upd(acc0[2], m[1], l[1]); upd(acc0[3], m[1], l[1]);
                upd(acc0[6], m[1], l[1]); upd(acc0[7], m[1], l[1]);
            }
            if (c1a > m[2] - 16.0f) {
                upd(acc1[0], m[2], l[2]); upd(acc1[1], m[2], l[2]);
                upd(acc1[4], m[2], l[2]); upd(acc1[5], m[2], l[2]);
            }
            if (c1b > m[3] - 16.0f) {
                upd(acc1[2], m[3], l[3]); upd(acc1[3], m[3], l[3]);
                upd(acc1[6], m[3], l[3]); upd(acc1[7], m[3], l[3]);
            }
        }
        __syncthreads();
    }

    // merge the 4 lanes of each quad (same row, disjoint k-cols)
    #pragma unroll
    for (int s = 0; s < 4; s++) {
        #pragma unroll
        for (int off = 1; off <= 2; off <<= 1) {
            float mo = __shfl_xor_sync(0xffffffffu, m[s], off);
            float lo = __shfl_xor_sync(0xffffffffu, l[s], off);
            float mm = fmaxf(m[s], mo);
            l[s] = l[s] * __expf(m[s] - mm) + lo * __expf(mo - mm);
            m[s] = mm;
        }
    }

    // cross-k-warp merge via smem: buf[wk][row]
    float2* buf = reinterpret_cast<float2*>(sm + S_RED);
    if ((lane & 3) == 0) {
        #pragma unroll
        for (int s = 0; s < 4; s++) {
            int row = wq * 32 + (s >> 1) * 16 + (s & 1) * 8 + (lane >> 2);
            buf[wk * 64 + row] = make_float2(m[s], l[s]);
        }
    }
    __syncthreads();

    if (tid < 64) {
        float2 a = buf[tid];
        float2 b = buf[64 + tid];
        float mm = fmaxf(a.x, b.x);
        float L = a.y * __expf(a.x - mm) + b.y * __expf(b.x - mm);
        g_ml[(size_t)grp * (KSPLIT * 64) + half * 64 + tid] = make_float2(mm, L);
    }
    __threadfence();
    __syncthreads();

    __shared__ unsigned int pos;
    if (tid == 0) pos = atomicAdd(&g_ticket2[grp], 1u);
    __syncthreads();
    if (pos != KSPLIT - 1) return;

    // second finisher: merge halves (deterministic), row LSE, group sum
    float* red = reinterpret_cast<float*>(sm + S_RED);
    {
        float A = 0.f;
        if (tid < 64) {
            const float2* base = g_ml + (size_t)grp * (KSPLIT * 64);
            float2 a = __ldcg(&base[tid]);
            float2 b = __ldcg(&base[64 + tid]);
            float mm = fmaxf(a.x, b.x);
            float L = a.y * __expf(a.x - mm) + b.y * __expf(b.x - mm);
            A = mm + logf(L);
        }
        __syncthreads();
        red[tid] = A;
        __syncthreads();
        if (tid < 32) {
            float s = red[tid] + red[tid + 32];
            #pragma unroll
            for (int off = 16; off > 0; off >>= 1)
                s += __shfl_xor_sync(0xffffffffu, s, off);
            if (tid == 0) g_partial[grp] = s;
        }
    }

    // global last-group election -> final deterministic sum of 384 partials
    __shared__ unsigned int is_last;
    __threadfence();
    if (tid == 0) is_last = (atomicAdd(&g_ticket, 1u) == NGRP - 1);
    __syncthreads();
    if (is_last) {
        __threadfence();
        float s = __ldcg(&g_partial[tid]) + __ldcg(&g_partial[tid + 128])
                + __ldcg(&g_partial[tid + 256]);
        red[tid] = s;
        __syncthreads();
        if (tid < 32) {
            float t = red[tid] + red[tid + 32] + red[tid + 64] + red[tid + 96];
            #pragma unroll
            for (int off = 16; off > 0; off >>= 1)
                t += __shfl_xor_sync(0xffffffffu, t, off);
            if (tid == 0) out[0] = -8.0f * t;
        }
    }
}

extern "C" void kernel_launch(void* const* d_in, const int* in_sizes, int n_in,
                              void* d_out, int out_size)
{
    (void)in_sizes; (void)n_in; (void)out_size;
    const float* g  = (const float*)d_in[0];
    const float* Wq = (const float*)d_in[1];
    const float* Wk = (const float*)d_in[2];
    float* out = (float*)d_out;

    const int convN = NG8 + 2 * NW8;
    conv_kernel<<<(convN + 255) / 256, 256>>>(g, Wq, Wk);
    proj_kernel<<<dim3(6, 32, 2), 128, P_SMEM>>>();
    scores_kernel<<<dim3(NQT, HH, KSPLIT), 128, S_SMEM>>>(out);
}

// round 10
// speedup vs baseline: 1.3380x; 1.3380x over previous
#include <cuda_runtime.h>
#include <cuda_bf16.h>
#include <cstdint>
#include <math.h>

#define NN 2048
#define DD 768
#define HH 12
#define YY 64

#define NQT 32                 // q-tiles per head (qtile = 64 rows)
#define NGRP (HH * NQT)        // 384 (h, qt) groups
#define KSPLIT 4               // K-range quarters per group
#define KCH (NN / KSPLIT / 128)// 4 chunks of 128 per CTA

// ---------------------------------------------------------------------------
// Scratch (__device__ globals; no allocation allowed)
// ---------------------------------------------------------------------------
__device__ __nv_bfloat16 g_gb [NN * DD];       // g in bf16
__device__ __nv_bfloat16 g_Wqb[HH * YY * DD];  // Wq in bf16
__device__ __nv_bfloat16 g_Wkb[HH * YY * DD];  // Wk in bf16
__device__ __nv_bfloat16 g_Q[HH * NN * YY];    // [h][n][y], pre-scaled by beta
__device__ __nv_bfloat16 g_K[HH * NN * YY];    // [h][n][y]
__device__ float2 g_ml[NGRP * KSPLIT * 64];    // per-row (m,l) per split
__device__ float g_partial[NGRP];              // per-group LSE row sums
__device__ unsigned int g_ticket2[NGRP];       // per-group split election
__device__ unsigned int g_ticket;              // global last-group election

// ---------------------------------------------------------------------------
// Helpers (standard sm_80+ features: ldmatrix / mma.sync / cp.async)
// ---------------------------------------------------------------------------
__device__ __forceinline__ uint32_t smem_u32(const void* p) {
    uint32_t a;
    asm("{ .reg .u64 t; cvta.to.shared.u64 t, %1; cvt.u32.u64 %0, t; }" : "=r"(a) : "l"(p));
    return a;
}

__device__ __forceinline__ void cpa16(uint32_t dst, const void* src) {
    asm volatile("cp.async.cg.shared.global [%0], [%1], 16;" :: "r"(dst), "l"(src));
}
#define CP_COMMIT() asm volatile("cp.async.commit_group;" ::: "memory")
#define CP_WAIT(n)  asm volatile("cp.async.wait_group %0;" :: "n"(n) : "memory")

__device__ __forceinline__ void ldsm4(uint32_t& r0, uint32_t& r1, uint32_t& r2, uint32_t& r3,
                                      uint32_t addr) {
    asm volatile("ldmatrix.sync.aligned.m8n8.x4.shared.b16 {%0,%1,%2,%3}, [%4];"
                 : "=r"(r0), "=r"(r1), "=r"(r2), "=r"(r3) : "r"(addr));
}

__device__ __forceinline__ void mma16816(float* c, const uint32_t* a, uint32_t b0, uint32_t b1) {
    asm volatile(
        "mma.sync.aligned.m16n8k16.row.col.f32.bf16.bf16.f32 "
        "{%0,%1,%2,%3}, {%4,%5,%6,%7}, {%8,%9}, {%0,%1,%2,%3};"
        : "+f"(c[0]), "+f"(c[1]), "+f"(c[2]), "+f"(c[3])
        : "r"(a[0]), "r"(a[1]), "r"(a[2]), "r"(a[3]), "r"(b0), "r"(b1));
}

__device__ __forceinline__ uint32_t bf16x2(float hi, float lo) {
    uint32_t r;
    asm("cvt.rn.bf16x2.f32 %0, %1, %2;" : "=r"(r) : "f"(hi), "f"(lo));
    return r;
}

// ---------------------------------------------------------------------------
// Convert f32 inputs -> bf16 globals; reset tickets for this launch.
// ---------------------------------------------------------------------------
#define NG8 (NN * DD / 8)          // 196608
#define NW8 (HH * YY * DD / 8)     // 73728

__global__ void __launch_bounds__(256) conv_kernel(const float* __restrict__ g,
                                                   const float* __restrict__ wq,
                                                   const float* __restrict__ wk)
{
    int i = blockIdx.x * 256 + threadIdx.x;
    if (i == 0) g_ticket = 0;
    if (i < NGRP) g_ticket2[i] = 0;
    const float* src;
    __nv_bfloat16* dst;
    int j;
    if (i < NG8)                { src = g;  dst = g_gb;  j = i; }
    else if (i < NG8 + NW8)     { src = wq; dst = g_Wqb; j = i - NG8; }
    else if (i < NG8 + 2 * NW8) { src = wk; dst = g_Wkb; j = i - NG8 - NW8; }
    else return;
    float4 v0 = *reinterpret_cast<const float4*>(src + (size_t)j * 8);
    float4 v1 = *reinterpret_cast<const float4*>(src + (size_t)j * 8 + 4);
    uint4 o;
    o.x = bf16x2(v0.y, v0.x);
    o.y = bf16x2(v0.w, v0.z);
    o.z = bf16x2(v1.y, v1.x);
    o.w = bf16x2(v1.w, v1.z);
    *reinterpret_cast<uint4*>(dst + (size_t)j * 8) = o;
}

// ---------------------------------------------------------------------------
// Projection: Out[c][n] for c = h*64+y.  Out = g . W^T.   (R8 version)
// CTA tile 64n x 128c, 128 threads (4 warps: 2m x 2n, warp tile 32x64).
// k-chunk 32 (pitch 80B). grid (6, 32, 2) = 384 CTAs.
// Dynamic smem: 2*(5120 + 10240) = 30720 B.
// ---------------------------------------------------------------------------
#define PROWB 80
#define PA_TILE (64 * PROWB)                // 5120 B
#define PB_TILE (128 * PROWB)               // 10240 B
#define P_STAGE (PA_TILE + PB_TILE)         // 15360 B
#define P_SMEM (2 * P_STAGE)                // 30720 B

__global__ void __launch_bounds__(128) proj_kernel()
{
    extern __shared__ char sm[];
    const uint32_t sb = smem_u32(sm);
    const int tid = threadIdx.x, lane = tid & 31, wid = tid >> 5;
    const int wm = wid & 1, wn = wid >> 1;
    const int c0 = blockIdx.x * 128, n0 = blockIdx.y * 64;
    const __nv_bfloat16* __restrict__ A = g_gb;
    const __nv_bfloat16* __restrict__ B = blockIdx.z ? g_Wkb : g_Wqb;
    __nv_bfloat16* __restrict__ Out = blockIdx.z ? g_K : g_Q;
    const float scale = blockIdx.z ? 1.0f : 0.125f;

    auto load_chunk = [&](int ch) {
        const int d0 = ch * 32;
        const uint32_t abuf = sb + (ch & 1) * P_STAGE;
        const uint32_t bbuf = abuf + PA_TILE;
        #pragma unroll
        for (int i = 0; i < 2; i++) {
            int gi = tid + i * 128;
            int r = gi >> 2, c = gi & 3;
            cpa16(abuf + r * PROWB + c * 16, A + (size_t)(n0 + r) * DD + d0 + c * 8);
        }
        #pragma unroll
        for (int i = 0; i < 4; i++) {
            int gi = tid + i * 128;
            int r = gi >> 2, c = gi & 3;
            cpa16(bbuf + r * PROWB + c * 16, B + (size_t)(c0 + r) * DD + d0 + c * 8);
        }
    };

    float acc[2][8][4];
    #pragma unroll
    for (int mt = 0; mt < 2; mt++)
        #pragma unroll
        for (int nt = 0; nt < 8; nt++)
            #pragma unroll
            for (int k = 0; k < 4; k++) acc[mt][nt][k] = 0.f;

    const int lr = lane & 7;
    const uint32_t aoff = (uint32_t)((wm * 32 + lr + ((lane >> 3) & 1) * 8) * PROWB
                                     + ((lane >> 4) & 1) * 16);
    const uint32_t boff = (uint32_t)((wn * 64 + lr + ((lane >> 4) & 1) * 8) * PROWB
                                     + ((lane >> 3) & 1) * 16);

    load_chunk(0); CP_COMMIT();

    for (int ch = 0; ch < 24; ch++) {
        if (ch < 23) { load_chunk(ch + 1); CP_COMMIT(); CP_WAIT(1); }
        else CP_WAIT(0);
        __syncthreads();

        const uint32_t abase = sb + (ch & 1) * P_STAGE + aoff;
        const uint32_t bbase = sb + (ch & 1) * P_STAGE + PA_TILE + boff;
        #pragma unroll
        for (int ks = 0; ks < 2; ks++) {
            uint32_t a0[4], a1[4];
            ldsm4(a0[0], a0[1], a0[2], a0[3], abase + ks * 32);
            ldsm4(a1[0], a1[1], a1[2], a1[3], abase + 16 * PROWB + ks * 32);
            #pragma unroll
            for (int ntp = 0; ntp < 4; ntp++) {
                uint32_t b0, b1, b2, b3;
                ldsm4(b0, b1, b2, b3, bbase + ntp * 16 * PROWB + ks * 32);
                mma16816(acc[0][2 * ntp],     a0, b0, b1);
                mma16816(acc[1][2 * ntp],     a1, b0, b1);
                mma16816(acc[0][2 * ntp + 1], a0, b2, b3);
                mma16816(acc[1][2 * ntp + 1], a1, b2, b3);
            }
        }
        __syncthreads();
    }

    const int h = (c0 >> 6) + wn;
    const int rbase = n0 + wm * 32 + (lane >> 2);
    #pragma unroll
    for (int mt = 0; mt < 2; mt++) {
        #pragma unroll
        for (int nt = 0; nt < 8; nt++) {
            const int y = nt * 8 + (lane & 3) * 2;
            const int n1 = rbase + mt * 16;
            uint32_t p0 = bf16x2(acc[mt][nt][1] * scale, acc[mt][nt][0] * scale);
            uint32_t p1 = bf16x2(acc[mt][nt][3] * scale, acc[mt][nt][2] * scale);
            *reinterpret_cast<uint32_t*>(&Out[((size_t)h * NN + n1) * YY + y])     = p0;
            *reinterpret_cast<uint32_t*>(&Out[((size_t)h * NN + n1 + 8) * YY + y]) = p1;
        }
    }
}

// ---------------------------------------------------------------------------
// Fused scores + LSE, split-K (KSPLIT=4). CTA per (qtile 64, head, K-quarter).
// R8 per-warp mainloop (4 warps x 16 q-rows), 4 K-chunks per CTA.
// grid (32, 12, 4) = 1536 CTAs of 128 threads.
// ---------------------------------------------------------------------------
#define ROWB 144
#define S_TILE (128 * ROWB)                 // 18432 B
#define S_RED  (2 * S_TILE)
#define S_SMEM (S_RED + 128 * 4)            // 37376 B

__global__ void __launch_bounds__(128) scores_kernel(float* __restrict__ out)
{
    extern __shared__ char sm[];
    const uint32_t sb = smem_u32(sm);
    const int tid = threadIdx.x, lane = tid & 31, wid = tid >> 5;
    const int h = blockIdx.y, qt = blockIdx.x, half = blockIdx.z;
    const int grp = h * NQT + qt;

    const __nv_bfloat16* __restrict__ Qsrc = g_Q + ((size_t)h * NN + qt * 64) * YY;
    const __nv_bfloat16* __restrict__ Ksrc = g_K + (size_t)h * NN * YY
                                           + (size_t)half * (NN / KSPLIT) * YY;

    auto load_q = [&]() {
        #pragma unroll
        for (int i = 0; i < 4; i++) {
            int gi = tid + i * 128;
            int r = gi >> 3, c = gi & 7;
            cpa16(sb + r * ROWB + c * 16, Qsrc + (size_t)r * YY + c * 8);
        }
    };
    auto load_k = [&](int ch) {
        const int k0 = ch * 128;
        const uint32_t buf = sb + (ch & 1) * S_TILE;
        #pragma unroll
        for (int i = 0; i < 8; i++) {
            int gi = tid + i * 128;
            int r = gi >> 3, c = gi & 7;
            cpa16(buf + r * ROWB + c * 16, Ksrc + (size_t)(k0 + r) * YY + c * 8);
        }
    };

    const int lr = lane & 7;
    const uint32_t aoff = (uint32_t)((wid * 16 + lr + ((lane >> 3) & 1) * 8) * ROWB
                                     + ((lane >> 4) & 1) * 16);
    const uint32_t boff = (uint32_t)((lr + ((lane >> 4) & 1) * 8) * ROWB
                                     + ((lane >> 3) & 1) * 16);

    // Stage Q through buffer 0, pull fragments into registers, then free it.
    load_q(); CP_COMMIT(); CP_WAIT(0);
    __syncthreads();
    uint32_t aR[4][4];
    #pragma unroll
    for (int ks = 0; ks < 4; ks++)
        ldsm4(aR[ks][0], aR[ks][1], aR[ks][2], aR[ks][3], sb + aoff + ks * 32);
    __syncthreads();

    load_k(0); CP_COMMIT();

    float m0 = -INFINITY, l0 = 0.f;   // row a = wid*16 + (lane>>2)
    float m1 = -INFINITY, l1 = 0.f;   // row b = row a + 8

    auto upd = [](float v, float& m, float& l) {
        if (v > m) { l = l * __expf(m - v) + 1.0f; m = v; }
        else if (v > m - 16.0f) { l += __expf(v - m); }
    };

    for (int ch = 0; ch < KCH; ch++) {
        if (ch < KCH - 1) { load_k(ch + 1); CP_COMMIT(); CP_WAIT(1); }
        else CP_WAIT(0);
        __syncthreads();

        const uint32_t bbase = sb + (ch & 1) * S_TILE + boff;
        #pragma unroll
        for (int ntp = 0; ntp < 8; ntp++) {
            float acc[8];
            #pragma unroll
            for (int j = 0; j < 8; j++) acc[j] = 0.f;
            #pragma unroll
            for (int ks = 0; ks < 4; ks++) {
                uint32_t b0, b1, b2, b3;
                ldsm4(b0, b1, b2, b3, bbase + ntp * 16 * ROWB + ks * 32);
                mma16816(acc,     aR[ks], b0, b1);
                mma16816(acc + 4, aR[ks], b2, b3);
            }
            float ca = fmaxf(fmaxf(acc[0], acc[1]), fmaxf(acc[4], acc[5]));
            float cb = fmaxf(fmaxf(acc[2], acc[3]), fmaxf(acc[6], acc[7]));
            if (ca > m0 - 16.0f) {
                upd(acc[0], m0, l0); upd(acc[1], m0, l0);
                upd(acc[4], m0, l0); upd(acc[5], m0, l0);
            }
            if (cb > m1 - 16.0f) {
                upd(acc[2], m1, l1); upd(acc[3], m1, l1);
                upd(acc[6], m1, l1); upd(acc[7], m1, l1);
            }
        }
        __syncthreads();
    }

    // combine the 4 lanes of each quad-row (same row, disjoint k-cols)
    #pragma unroll
    for (int off = 1; off <= 2; off <<= 1) {
        float mo = __shfl_xor_sync(0xffffffffu, m0, off);
        float lo = __shfl_xor_sync(0xffffffffu, l0, off);
        float mm = fmaxf(m0, mo);
        l0 = l0 * __expf(m0 - mm) + lo * __expf(mo - mm);
        m0 = mm;
        mo = __shfl_xor_sync(0xffffffffu, m1, off);
        lo = __shfl_xor_sync(0xffffffffu, l1, off);
        mm = fmaxf(m1, mo);
        l1 = l1 * __expf(m1 - mm) + lo * __expf(mo - mm);
        m1 = mm;
    }

    // publish per-row (m,l) for this split
    float2* gml = g_ml + (size_t)grp * (KSPLIT * 64) + half * 64;
    if ((lane & 3) == 0) {
        int row = wid * 16 + (lane >> 2);
        gml[row]     = make_float2(m0, l0);
        gml[row + 8] = make_float2(m1, l1);
    }
    __threadfence();
    __syncthreads();

    __shared__ unsigned int pos;
    if (tid == 0) pos = atomicAdd(&g_ticket2[grp], 1u);
    __syncthreads();
    if (pos != KSPLIT - 1) return;

    // last finisher: merge KSPLIT splits in fixed order (deterministic),
    // row LSE, group sum
    float* red = reinterpret_cast<float*>(sm + S_RED);
    {
        float A = 0.f;
        if (tid < 64) {
            const float2* base = g_ml + (size_t)grp * (KSPLIT * 64);
            float2 a = __ldcg(&base[tid]);
            float mm = a.x;
            float L = a.y;
            #pragma unroll
            for (int s = 1; s < KSPLIT; s++) {
                float2 b = __ldcg(&base[s * 64 + tid]);
                float mn = fmaxf(mm, b.x);
                L = L * __expf(mm - mn) + b.y * __expf(b.x - mn);
                mm = mn;
            }
            A = mm + logf(L);
        }
        red[tid] = A;
        __syncthreads();
        if (tid < 32) {
            float s = red[tid] + red[tid + 32];
            #pragma unroll
            for (int off = 16; off > 0; off >>= 1)
                s += __shfl_xor_sync(0xffffffffu, s, off);
            if (tid == 0) g_partial[grp] = s;
        }
    }

    // global last-group election -> final deterministic sum of 384 partials
    __shared__ unsigned int is_last;
    __threadfence();
    if (tid == 0) is_last = (atomicAdd(&g_ticket, 1u) == NGRP - 1);
    __syncthreads();
    if (is_last) {
        __threadfence();
        float s = __ldcg(&g_partial[tid]) + __ldcg(&g_partial[tid + 128])
                + __ldcg(&g_partial[tid + 256]);
        red[tid] = s;
        __syncthreads();
        if (tid < 32) {
            float t = red[tid] + red[tid + 32] + red[tid + 64] + red[tid + 96];
            #pragma unroll
            for (int off = 16; off > 0; off >>= 1)
                t += __shfl_xor_sync(0xffffffffu, t, off);
            if (tid == 0) out[0] = -8.0f * t;
        }
    }
}

extern "C" void kernel_launch(void* const* d_in, const int* in_sizes, int n_in,
                              void* d_out, int out_size)
{
    (void)in_sizes; (void)n_in; (void)out_size;
    const float* g  = (const float*)d_in[0];
    const float* Wq = (const float*)d_in[1];
    const float* Wk = (const float*)d_in[2];
    float* out = (float*)d_out;

    const int convN = NG8 + 2 * NW8;
    conv_kernel<<<(convN + 255) / 256, 256>>>(g, Wq, Wk);
    proj_kernel<<<dim3(6, 32, 2), 128, P_SMEM>>>();
    scores_kernel<<<dim3(NQT, HH, KSPLIT), 128, S_SMEM>>>(out);
}

// round 11
// speedup vs baseline: 1.3894x; 1.0384x over previous
#include <cuda_runtime.h>
#include <cuda_bf16.h>
#include <cstdint>
#include <math.h>

#define NN 2048
#define DD 768
#define HH 12
#define YY 64

#define NQT 32                 // q-tiles per head (qtile = 64 rows)
#define NGRP (HH * NQT)        // 384 (h, qt) groups
#define KSPLIT 2               // K-range halves per group
#define KCH (NN / KSPLIT / 128)// 8 chunks of 128 per CTA

// ---------------------------------------------------------------------------
// Scratch (__device__ globals; no allocation allowed)
// ---------------------------------------------------------------------------
__device__ __nv_bfloat16 g_gb [NN * DD];       // g in bf16
__device__ __nv_bfloat16 g_Wqb[HH * YY * DD];  // Wq in bf16
__device__ __nv_bfloat16 g_Wkb[HH * YY * DD];  // Wk in bf16
__device__ uint8_t g_Q8[HH * NN * YY];         // [h][n][y] e4m3, pre-scaled by beta
__device__ uint8_t g_K8[HH * NN * YY];         // [h][n][y] e4m3
__device__ float2 g_ml[NGRP * KSPLIT * 64];    // per-row (m,l) per half
__device__ float g_partial[NGRP];              // per-group LSE row sums
__device__ unsigned int g_ticket2[NGRP];       // per-group pair election
__device__ unsigned int g_ticket;              // global last-group election

// ---------------------------------------------------------------------------
// Helpers (standard sm_80/89 features: ldmatrix / mma.sync / cp.async / fp8)
// ---------------------------------------------------------------------------
__device__ __forceinline__ uint32_t smem_u32(const void* p) {
    uint32_t a;
    asm("{ .reg .u64 t; cvta.to.shared.u64 t, %1; cvt.u32.u64 %0, t; }" : "=r"(a) : "l"(p));
    return a;
}

__device__ __forceinline__ void cpa16(uint32_t dst, const void* src) {
    asm volatile("cp.async.cg.shared.global [%0], [%1], 16;" :: "r"(dst), "l"(src));
}
#define CP_COMMIT() asm volatile("cp.async.commit_group;" ::: "memory")
#define CP_WAIT(n)  asm volatile("cp.async.wait_group %0;" :: "n"(n) : "memory")

__device__ __forceinline__ void ldsm4(uint32_t& r0, uint32_t& r1, uint32_t& r2, uint32_t& r3,
                                      uint32_t addr) {
    asm volatile("ldmatrix.sync.aligned.m8n8.x4.shared.b16 {%0,%1,%2,%3}, [%4];"
                 : "=r"(r0), "=r"(r1), "=r"(r2), "=r"(r3) : "r"(addr));
}

__device__ __forceinline__ void mma16816(float* c, const uint32_t* a, uint32_t b0, uint32_t b1) {
    asm volatile(
        "mma.sync.aligned.m16n8k16.row.col.f32.bf16.bf16.f32 "
        "{%0,%1,%2,%3}, {%4,%5,%6,%7}, {%8,%9}, {%0,%1,%2,%3};"
        : "+f"(c[0]), "+f"(c[1]), "+f"(c[2]), "+f"(c[3])
        : "r"(a[0]), "r"(a[1]), "r"(a[2]), "r"(a[3]), "r"(b0), "r"(b1));
}

// fp8 e4m3 MMA: m16n8k32, fragment layout == m16n8k16.f16 with 2 fp8 per b16 slot
__device__ __forceinline__ void mma16832f8(float* c, const uint32_t* a, uint32_t b0, uint32_t b1) {
    asm volatile(
        "mma.sync.aligned.m16n8k32.row.col.f32.e4m3.e4m3.f32 "
        "{%0,%1,%2,%3}, {%4,%5,%6,%7}, {%8,%9}, {%0,%1,%2,%3};"
        : "+f"(c[0]), "+f"(c[1]), "+f"(c[2]), "+f"(c[3])
        : "r"(a[0]), "r"(a[1]), "r"(a[2]), "r"(a[3]), "r"(b0), "r"(b1));
}

__device__ __forceinline__ uint32_t bf16x2(float hi, float lo) {
    uint32_t r;
    asm("cvt.rn.bf16x2.f32 %0, %1, %2;" : "=r"(r) : "f"(hi), "f"(lo));
    return r;
}

// pack two floats into e4m3x2 (hi -> upper byte, lo -> lower byte)
__device__ __forceinline__ unsigned short e4m3x2(float hi, float lo) {
    unsigned short r;
    asm("{ .reg .b16 t; cvt.rn.satfinite.e4m3x2.f32 t, %1, %2; mov.b16 %0, t; }"
        : "=h"(r) : "f"(hi), "f"(lo));
    return r;
}

// ---------------------------------------------------------------------------
// Convert f32 inputs -> bf16 globals; reset tickets for this launch.
// ---------------------------------------------------------------------------
#define NG8 (NN * DD / 8)          // 196608
#define NW8 (HH * YY * DD / 8)     // 73728

__global__ void __launch_bounds__(256) conv_kernel(const float* __restrict__ g,
                                                   const float* __restrict__ wq,
                                                   const float* __restrict__ wk)
{
    int i = blockIdx.x * 256 + threadIdx.x;
    if (i == 0) g_ticket = 0;
    if (i < NGRP) g_ticket2[i] = 0;
    const float* src;
    __nv_bfloat16* dst;
    int j;
    if (i < NG8)                { src = g;  dst = g_gb;  j = i; }
    else if (i < NG8 + NW8)     { src = wq; dst = g_Wqb; j = i - NG8; }
    else if (i < NG8 + 2 * NW8) { src = wk; dst = g_Wkb; j = i - NG8 - NW8; }
    else return;
    float4 v0 = *reinterpret_cast<const float4*>(src + (size_t)j * 8);
    float4 v1 = *reinterpret_cast<const float4*>(src + (size_t)j * 8 + 4);
    uint4 o;
    o.x = bf16x2(v0.y, v0.x);
    o.y = bf16x2(v0.w, v0.z);
    o.z = bf16x2(v1.y, v1.x);
    o.w = bf16x2(v1.w, v1.z);
    *reinterpret_cast<uint4*>(dst + (size_t)j * 8) = o;
}

// ---------------------------------------------------------------------------
// Projection: Out[c][n] for c = h*64+y.  Out = g . W^T.   (R8 mainloop)
// CTA tile 64n x 128c, 128 threads (4 warps: 2m x 2n, warp tile 32x64).
// k-chunk 32 (pitch 80B). grid (6, 32, 2) = 384 CTAs.
// Epilogue emits packed e4m3 (Q pre-scaled by beta).
// ---------------------------------------------------------------------------
#define PROWB 80
#define PA_TILE (64 * PROWB)                // 5120 B
#define PB_TILE (128 * PROWB)               // 10240 B
#define P_STAGE (PA_TILE + PB_TILE)         // 15360 B
#define P_SMEM (2 * P_STAGE)                // 30720 B

__global__ void __launch_bounds__(128) proj_kernel()
{
    extern __shared__ char sm[];
    const uint32_t sb = smem_u32(sm);
    const int tid = threadIdx.x, lane = tid & 31, wid = tid >> 5;
    const int wm = wid & 1, wn = wid >> 1;
    const int c0 = blockIdx.x * 128, n0 = blockIdx.y * 64;
    const __nv_bfloat16* __restrict__ A = g_gb;
    const __nv_bfloat16* __restrict__ B = blockIdx.z ? g_Wkb : g_Wqb;
    uint8_t* __restrict__ Out = blockIdx.z ? g_K8 : g_Q8;
    const float scale = blockIdx.z ? 1.0f : 0.125f;

    auto load_chunk = [&](int ch) {
        const int d0 = ch * 32;
        const uint32_t abuf = sb + (ch & 1) * P_STAGE;
        const uint32_t bbuf = abuf + PA_TILE;
        #pragma unroll
        for (int i = 0; i < 2; i++) {
            int gi = tid + i * 128;
            int r = gi >> 2, c = gi & 3;
            cpa16(abuf + r * PROWB + c * 16, A + (size_t)(n0 + r) * DD + d0 + c * 8);
        }
        #pragma unroll
        for (int i = 0; i < 4; i++) {
            int gi = tid + i * 128;
            int r = gi >> 2, c = gi & 3;
            cpa16(bbuf + r * PROWB + c * 16, B + (size_t)(c0 + r) * DD + d0 + c * 8);
        }
    };

    float acc[2][8][4];
    #pragma unroll
    for (int mt = 0; mt < 2; mt++)
        #pragma unroll
        for (int nt = 0; nt < 8; nt++)
            #pragma unroll
            for (int k = 0; k < 4; k++) acc[mt][nt][k] = 0.f;

    const int lr = lane & 7;
    const uint32_t aoff = (uint32_t)((wm * 32 + lr + ((lane >> 3) & 1) * 8) * PROWB
                                     + ((lane >> 4) & 1) * 16);
    const uint32_t boff = (uint32_t)((wn * 64 + lr + ((lane >> 4) & 1) * 8) * PROWB
                                     + ((lane >> 3) & 1) * 16);

    load_chunk(0); CP_COMMIT();

    for (int ch = 0; ch < 24; ch++) {
        if (ch < 23) { load_chunk(ch + 1); CP_COMMIT(); CP_WAIT(1); }
        else CP_WAIT(0);
        __syncthreads();

        const uint32_t abase = sb + (ch & 1) * P_STAGE + aoff;
        const uint32_t bbase = sb + (ch & 1) * P_STAGE + PA_TILE + boff;
        #pragma unroll
        for (int ks = 0; ks < 2; ks++) {
            uint32_t a0[4], a1[4];
            ldsm4(a0[0], a0[1], a0[2], a0[3], abase + ks * 32);
            ldsm4(a1[0], a1[1], a1[2], a1[3], abase + 16 * PROWB + ks * 32);
            #pragma unroll
            for (int ntp = 0; ntp < 4; ntp++) {
                uint32_t b0, b1, b2, b3;
                ldsm4(b0, b1, b2, b3, bbase + ntp * 16 * PROWB + ks * 32);
                mma16816(acc[0][2 * ntp],     a0, b0, b1);
                mma16816(acc[1][2 * ntp],     a1, b0, b1);
                mma16816(acc[0][2 * ntp + 1], a0, b2, b3);
                mma16816(acc[1][2 * ntp + 1], a1, b2, b3);
            }
        }
        __syncthreads();
    }

    const int h = (c0 >> 6) + wn;
    const int rbase = n0 + wm * 32 + (lane >> 2);
    #pragma unroll
    for (int mt = 0; mt < 2; mt++) {
        #pragma unroll
        for (int nt = 0; nt < 8; nt++) {
            const int y = nt * 8 + (lane & 3) * 2;
            const int n1 = rbase + mt * 16;
            unsigned short p0 = e4m3x2(acc[mt][nt][1] * scale, acc[mt][nt][0] * scale);
            unsigned short p1 = e4m3x2(acc[mt][nt][3] * scale, acc[mt][nt][2] * scale);
            *reinterpret_cast<unsigned short*>(&Out[((size_t)h * NN + n1) * YY + y])     = p0;
            *reinterpret_cast<unsigned short*>(&Out[((size_t)h * NN + n1 + 8) * YY + y]) = p1;
        }
    }
}

// ---------------------------------------------------------------------------
// Fused scores + LSE, split-K (KSPLIT=2), fp8 e4m3 MMA (m16n8k32).
// CTA per (qtile 64, head, K-half); 4 warps x 16 q-rows; 8 K-chunks per CTA.
// Rows are 64 fp8 = 64B, pitch 80B (conflict-free ldsm). Per ntp: 2 LDSM +
// 4 MMA (halved vs bf16). grid (32, 12, 2) = 768 CTAs of 128 threads.
// ---------------------------------------------------------------------------
#define ROWB 80
#define S_TILE (128 * ROWB)                 // 10240 B
#define S_RED  (2 * S_TILE)
#define S_SMEM (S_RED + 128 * 4)            // 20992 B

__global__ void __launch_bounds__(128) scores_kernel(float* __restrict__ out)
{
    extern __shared__ char sm[];
    const uint32_t sb = smem_u32(sm);
    const int tid = threadIdx.x, lane = tid & 31, wid = tid >> 5;
    const int h = blockIdx.y, qt = blockIdx.x, half = blockIdx.z;
    const int grp = h * NQT + qt;

    const uint8_t* __restrict__ Qsrc = g_Q8 + ((size_t)h * NN + qt * 64) * YY;
    const uint8_t* __restrict__ Ksrc = g_K8 + (size_t)h * NN * YY
                                     + (size_t)half * (NN / KSPLIT) * YY;

    // Q tile 64 rows x 64B: 256 granules -> 2 per thread
    auto load_q = [&]() {
        #pragma unroll
        for (int i = 0; i < 2; i++) {
            int gi = tid + i * 128;
            int r = gi >> 2, c = gi & 3;
            cpa16(sb + r * ROWB + c * 16, Qsrc + (size_t)r * YY + c * 16);
        }
    };
    // K chunk 128 rows x 64B: 512 granules -> 4 per thread
    auto load_k = [&](int ch) {
        const int k0 = ch * 128;
        const uint32_t buf = sb + (ch & 1) * S_TILE;
        #pragma unroll
        for (int i = 0; i < 4; i++) {
            int gi = tid + i * 128;
            int r = gi >> 2, c = gi & 3;
            cpa16(buf + r * ROWB + c * 16, Ksrc + (size_t)(k0 + r) * YY + c * 16);
        }
    };

    const int lr = lane & 7;
    const uint32_t aoff = (uint32_t)((wid * 16 + lr + ((lane >> 3) & 1) * 8) * ROWB
                                     + ((lane >> 4) & 1) * 16);
    const uint32_t boff = (uint32_t)((lr + ((lane >> 4) & 1) * 8) * ROWB
                                     + ((lane >> 3) & 1) * 16);

    // Stage Q through buffer 0, pull fragments into registers, then free it.
    load_q(); CP_COMMIT(); CP_WAIT(0);
    __syncthreads();
    uint32_t aR[2][4];   // 2 k32-steps x 4 regs
    #pragma unroll
    for (int ks = 0; ks < 2; ks++)
        ldsm4(aR[ks][0], aR[ks][1], aR[ks][2], aR[ks][3], sb + aoff + ks * 32);
    __syncthreads();

    load_k(0); CP_COMMIT();

    float m0 = -INFINITY, l0 = 0.f;   // row a = wid*16 + (lane>>2)
    float m1 = -INFINITY, l1 = 0.f;   // row b = row a + 8

    auto upd = [](float v, float& m, float& l) {
        if (v > m) { l = l * __expf(m - v) + 1.0f; m = v; }
        else if (v > m - 16.0f) { l += __expf(v - m); }
    };

    for (int ch = 0; ch < KCH; ch++) {
        if (ch < KCH - 1) { load_k(ch + 1); CP_COMMIT(); CP_WAIT(1); }
        else CP_WAIT(0);
        __syncthreads();

        const uint32_t bbase = sb + (ch & 1) * S_TILE + boff;
        #pragma unroll
        for (int ntp = 0; ntp < 8; ntp++) {
            float acc[8];
            #pragma unroll
            for (int j = 0; j < 8; j++) acc[j] = 0.f;
            #pragma unroll
            for (int ks = 0; ks < 2; ks++) {
                uint32_t b0, b1, b2, b3;
                ldsm4(b0, b1, b2, b3, bbase + ntp * 16 * ROWB + ks * 32);
                mma16832f8(acc,     aR[ks], b0, b1);
                mma16832f8(acc + 4, aR[ks], b2, b3);
            }
            float ca = fmaxf(fmaxf(acc[0], acc[1]), fmaxf(acc[4], acc[5]));
            float cb = fmaxf(fmaxf(acc[2], acc[3]), fmaxf(acc[6], acc[7]));
            if (ca > m0 - 16.0f) {
                upd(acc[0], m0, l0); upd(acc[1], m0, l0);
                upd(acc[4], m0, l0); upd(acc[5], m0, l0);
            }
            if (cb > m1 - 16.0f) {
                upd(acc[2], m1, l1); upd(acc[3], m1, l1);
                upd(acc[6], m1, l1); upd(acc[7], m1, l1);
            }
        }
        __syncthreads();
    }

    // combine the 4 lanes of each quad-row (same row, disjoint k-cols)
    #pragma unroll
    for (int off = 1; off <= 2; off <<= 1) {
        float mo = __shfl_xor_sync(0xffffffffu, m0, off);
        float lo = __shfl_xor_sync(0xffffffffu, l0, off);
        float mm = fmaxf(m0, mo);
        l0 = l0 * __expf(m0 - mm) + lo * __expf(mo - mm);
        m0 = mm;
        mo = __shfl_xor_sync(0xffffffffu, m1, off);
        lo = __shfl_xor_sync(0xffffffffu, l1, off);
        mm = fmaxf(m1, mo);
        l1 = l1 * __expf(m1 - mm) + lo * __expf(mo - mm);
        m1 = mm;
    }

    // publish per-row (m,l) for this half
    float2* gml = g_ml + (size_t)grp * (KSPLIT * 64) + half * 64;
    if ((lane & 3) == 0) {
        int row = wid * 16 + (lane >> 2);
        gml[row]     = make_float2(m0, l0);
        gml[row + 8] = make_float2(m1, l1);
    }
    __threadfence();
    __syncthreads();

    __shared__ unsigned int pos;
    if (tid == 0) pos = atomicAdd(&g_ticket2[grp], 1u);
    __syncthreads();
    if (pos != KSPLIT - 1) return;

    // second finisher: merge halves (deterministic), row LSE, group sum
    float* red = reinterpret_cast<float*>(sm + S_RED);
    {
        float A = 0.f;
        if (tid < 64) {
            const float2* base = g_ml + (size_t)grp * (KSPLIT * 64);
            float2 a = __ldcg(&base[tid]);
            float2 b = __ldcg(&base[64 + tid]);
            float mm = fmaxf(a.x, b.x);
            float L = a.y * __expf(a.x - mm) + b.y * __expf(b.x - mm);
            A = mm + logf(L);
        }
        red[tid] = A;
        __syncthreads();
        if (tid < 32) {
            float s = red[tid] + red[tid + 32];
            #pragma unroll
            for (int off = 16; off > 0; off >>= 1)
                s += __shfl_xor_sync(0xffffffffu, s, off);
            if (tid == 0) g_partial[grp] = s;
        }
    }

    // global last-group election -> final deterministic sum of 384 partials
    __shared__ unsigned int is_last;
    __threadfence();
    if (tid == 0) is_last = (atomicAdd(&g_ticket, 1u) == NGRP - 1);
    __syncthreads();
    if (is_last) {
        __threadfence();
        float s = __ldcg(&g_partial[tid]) + __ldcg(&g_partial[tid + 128])
                + __ldcg(&g_partial[tid + 256]);
        red[tid] = s;
        __syncthreads();
        if (tid < 32) {
            float t = red[tid] + red[tid + 32] + red[tid + 64] + red[tid + 96];
            #pragma unroll
            for (int off = 16; off > 0; off >>= 1)
                t += __shfl_xor_sync(0xffffffffu, t, off);
            if (tid == 0) out[0] = -8.0f * t;
        }
    }
}

extern "C" void kernel_launch(void* const* d_in, const int* in_sizes, int n_in,
                              void* d_out, int out_size)
{
    (void)in_sizes; (void)n_in; (void)out_size;
    const float* g  = (const float*)d_in[0];
    const float* Wq = (const float*)d_in[1];
    const float* Wk = (const float*)d_in[2];
    float* out = (float*)d_out;

    const int convN = NG8 + 2 * NW8;
    conv_kernel<<<(convN + 255) / 256, 256>>>(g, Wq, Wk);
    proj_kernel<<<dim3(6, 32, 2), 128, P_SMEM>>>();
    scores_kernel<<<dim3(NQT, HH, KSPLIT), 128, S_SMEM>>>(out);
}

// round 12
// speedup vs baseline: 1.4104x; 1.0151x over previous
#include <cuda_runtime.h>
#include <cuda_bf16.h>
#include <cstdint>
#include <math.h>

#define NN 2048
#define DD 768
#define HH 12
#define YY 64

#define NQT 32                 // q-tiles per head (qtile = 64 rows)
#define NGRP (HH * NQT)        // 384 (h, qt) groups
#define KSPLIT 2               // K-range halves per group
#define KCH (NN / KSPLIT / 128)// 8 chunks of 128 per CTA

// ---------------------------------------------------------------------------
// Scratch (__device__ globals; no allocation allowed)
// ---------------------------------------------------------------------------
__device__ __nv_bfloat16 g_gb [NN * DD];       // g in bf16
__device__ __nv_bfloat16 g_Wqb[HH * YY * DD];  // Wq in bf16
__device__ __nv_bfloat16 g_Wkb[HH * YY * DD];  // Wk in bf16
__device__ __nv_bfloat16 g_Q[HH * NN * YY];    // [h][n][y], pre-scaled by beta
__device__ __nv_bfloat16 g_K[HH * NN * YY];    // [h][n][y]
__device__ float2 g_ml[NGRP * KSPLIT * 64];    // per-row (m,l) per half
__device__ float g_partial[NGRP];              // per-group LSE row sums
__device__ unsigned int g_ticket2[NGRP];       // per-group pair election
__device__ unsigned int g_ticket;              // global last-group election

// ---------------------------------------------------------------------------
// Helpers (standard sm_80+ features: ldmatrix / mma.sync / cp.async)
// ---------------------------------------------------------------------------
__device__ __forceinline__ uint32_t smem_u32(const void* p) {
    uint32_t a;
    asm("{ .reg .u64 t; cvta.to.shared.u64 t, %1; cvt.u32.u64 %0, t; }" : "=r"(a) : "l"(p));
    return a;
}

__device__ __forceinline__ void cpa16(uint32_t dst, const void* src) {
    asm volatile("cp.async.cg.shared.global [%0], [%1], 16;" :: "r"(dst), "l"(src));
}
#define CP_COMMIT() asm volatile("cp.async.commit_group;" ::: "memory")
#define CP_WAIT(n)  asm volatile("cp.async.wait_group %0;" :: "n"(n) : "memory")

__device__ __forceinline__ void ldsm4(uint32_t& r0, uint32_t& r1, uint32_t& r2, uint32_t& r3,
                                      uint32_t addr) {
    asm volatile("ldmatrix.sync.aligned.m8n8.x4.shared.b16 {%0,%1,%2,%3}, [%4];"
                 : "=r"(r0), "=r"(r1), "=r"(r2), "=r"(r3) : "r"(addr));
}

__device__ __forceinline__ void mma16816(float* c, const uint32_t* a, uint32_t b0, uint32_t b1) {
    asm volatile(
        "mma.sync.aligned.m16n8k16.row.col.f32.bf16.bf16.f32 "
        "{%0,%1,%2,%3}, {%4,%5,%6,%7}, {%8,%9}, {%0,%1,%2,%3};"
        : "+f"(c[0]), "+f"(c[1]), "+f"(c[2]), "+f"(c[3])
        : "r"(a[0]), "r"(a[1]), "r"(a[2]), "r"(a[3]), "r"(b0), "r"(b1));
}

__device__ __forceinline__ uint32_t bf16x2(float hi, float lo) {
    uint32_t r;
    asm("cvt.rn.bf16x2.f32 %0, %1, %2;" : "=r"(r) : "f"(hi), "f"(lo));
    return r;
}

// ---------------------------------------------------------------------------
// Convert f32 inputs -> bf16 globals; reset tickets for this launch.
// Each thread: 4 granules of 8 elems = 32 elems; 8 independent LDG.128
// issued up-front (MLP=8) then 4 STG.128. Boundaries are granule-x4 aligned
// (NG8=196608, NW8=73728 both divisible by 4) so a thread never straddles.
// ---------------------------------------------------------------------------
#define NG8 (NN * DD / 8)          // 196608
#define NW8 (HH * YY * DD / 8)     // 73728
#define CONV_T ((NG8 + 2 * NW8) / 4)   // 86016 threads

__global__ void __launch_bounds__(256) conv_kernel(const float* __restrict__ g,
                                                   const float* __restrict__ wq,
                                                   const float* __restrict__ wk)
{
    int t = blockIdx.x * 256 + threadIdx.x;
    if (t == 0) g_ticket = 0;
    if (t < NGRP) g_ticket2[t] = 0;
    if (t >= CONV_T) return;
    int g0 = t * 4;                       // granule base
    const float* src;
    __nv_bfloat16* dst;
    int j;
    if (g0 < NG8)           { src = g;  dst = g_gb;  j = g0; }
    else if (g0 < NG8+NW8)  { src = wq; dst = g_Wqb; j = g0 - NG8; }
    else                    { src = wk; dst = g_Wkb; j = g0 - NG8 - NW8; }

    float4 v[8];
    #pragma unroll
    for (int k = 0; k < 8; k++)
        v[k] = *reinterpret_cast<const float4*>(src + (size_t)j * 8 + k * 4);
    #pragma unroll
    for (int k = 0; k < 4; k++) {
        uint4 o;
        o.x = bf16x2(v[2*k].y,   v[2*k].x);
        o.y = bf16x2(v[2*k].w,   v[2*k].z);
        o.z = bf16x2(v[2*k+1].y, v[2*k+1].x);
        o.w = bf16x2(v[2*k+1].w, v[2*k+1].z);
        *reinterpret_cast<uint4*>(dst + (size_t)(j + k) * 8) = o;
    }
}

// ---------------------------------------------------------------------------
// Projection: Out[c][n] for c = h*64+y.  Out = g . W^T.   (R8 version)
// CTA tile 64n x 128c, 128 threads (4 warps: 2m x 2n, warp tile 32x64).
// k-chunk 32 (pitch 80B). grid (6, 32, 2) = 384 CTAs.
// Dynamic smem: 2*(5120 + 10240) = 30720 B.
// ---------------------------------------------------------------------------
#define PROWB 80
#define PA_TILE (64 * PROWB)                // 5120 B
#define PB_TILE (128 * PROWB)               // 10240 B
#define P_STAGE (PA_TILE + PB_TILE)         // 15360 B
#define P_SMEM (2 * P_STAGE)                // 30720 B

__global__ void __launch_bounds__(128) proj_kernel()
{
    extern __shared__ char sm[];
    const uint32_t sb = smem_u32(sm);
    const int tid = threadIdx.x, lane = tid & 31, wid = tid >> 5;
    const int wm = wid & 1, wn = wid >> 1;
    const int c0 = blockIdx.x * 128, n0 = blockIdx.y * 64;
    const __nv_bfloat16* __restrict__ A = g_gb;
    const __nv_bfloat16* __restrict__ B = blockIdx.z ? g_Wkb : g_Wqb;
    __nv_bfloat16* __restrict__ Out = blockIdx.z ? g_K : g_Q;
    const float scale = blockIdx.z ? 1.0f : 0.125f;

    auto load_chunk = [&](int ch) {
        const int d0 = ch * 32;
        const uint32_t abuf = sb + (ch & 1) * P_STAGE;
        const uint32_t bbuf = abuf + PA_TILE;
        #pragma unroll
        for (int i = 0; i < 2; i++) {
            int gi = tid + i * 128;
            int r = gi >> 2, c = gi & 3;
            cpa16(abuf + r * PROWB + c * 16, A + (size_t)(n0 + r) * DD + d0 + c * 8);
        }
        #pragma unroll
        for (int i = 0; i < 4; i++) {
            int gi = tid + i * 128;
            int r = gi >> 2, c = gi & 3;
            cpa16(bbuf + r * PROWB + c * 16, B + (size_t)(c0 + r) * DD + d0 + c * 8);
        }
    };

    float acc[2][8][4];
    #pragma unroll
    for (int mt = 0; mt < 2; mt++)
        #pragma unroll
        for (int nt = 0; nt < 8; nt++)
            #pragma unroll
            for (int k = 0; k < 4; k++) acc[mt][nt][k] = 0.f;

    const int lr = lane & 7;
    const uint32_t aoff = (uint32_t)((wm * 32 + lr + ((lane >> 3) & 1) * 8) * PROWB
                                     + ((lane >> 4) & 1) * 16);
    const uint32_t boff = (uint32_t)((wn * 64 + lr + ((lane >> 4) & 1) * 8) * PROWB
                                     + ((lane >> 3) & 1) * 16);

    load_chunk(0); CP_COMMIT();

    for (int ch = 0; ch < 24; ch++) {
        if (ch < 23) { load_chunk(ch + 1); CP_COMMIT(); CP_WAIT(1); }
        else CP_WAIT(0);
        __syncthreads();

        const uint32_t abase = sb + (ch & 1) * P_STAGE + aoff;
        const uint32_t bbase = sb + (ch & 1) * P_STAGE + PA_TILE + boff;
        #pragma unroll
        for (int ks = 0; ks < 2; ks++) {
            uint32_t a0[4], a1[4];
            ldsm4(a0[0], a0[1], a0[2], a0[3], abase + ks * 32);
            ldsm4(a1[0], a1[1], a1[2], a1[3], abase + 16 * PROWB + ks * 32);
            #pragma unroll
            for (int ntp = 0; ntp < 4; ntp++) {
                uint32_t b0, b1, b2, b3;
                ldsm4(b0, b1, b2, b3, bbase + ntp * 16 * PROWB + ks * 32);
                mma16816(acc[0][2 * ntp],     a0, b0, b1);
                mma16816(acc[1][2 * ntp],     a1, b0, b1);
                mma16816(acc[0][2 * ntp + 1], a0, b2, b3);
                mma16816(acc[1][2 * ntp + 1], a1, b2, b3);
            }
        }
        __syncthreads();
    }

    const int h = (c0 >> 6) + wn;
    const int rbase = n0 + wm * 32 + (lane >> 2);
    #pragma unroll
    for (int mt = 0; mt < 2; mt++) {
        #pragma unroll
        for (int nt = 0; nt < 8; nt++) {
            const int y = nt * 8 + (lane & 3) * 2;
            const int n1 = rbase + mt * 16;
            uint32_t p0 = bf16x2(acc[mt][nt][1] * scale, acc[mt][nt][0] * scale);
            uint32_t p1 = bf16x2(acc[mt][nt][3] * scale, acc[mt][nt][2] * scale);
            *reinterpret_cast<uint32_t*>(&Out[((size_t)h * NN + n1) * YY + y])     = p0;
            *reinterpret_cast<uint32_t*>(&Out[((size_t)h * NN + n1 + 8) * YY + y]) = p1;
        }
    }
}

// ---------------------------------------------------------------------------
// Fused scores + LSE, split-K (KSPLIT=2). CTA per (qtile 64, head, K-half).
// R8 per-warp mainloop (4 warps x 16 q-rows), 8 K-chunks per CTA.
// grid (32, 12, 2) = 768 CTAs of 128 threads.
// ---------------------------------------------------------------------------
#define ROWB 144
#define S_TILE (128 * ROWB)                 // 18432 B
#define S_RED  (2 * S_TILE)
#define S_SMEM (S_RED + 128 * 4)            // 37376 B

__global__ void __launch_bounds__(128) scores_kernel(float* __restrict__ out)
{
    extern __shared__ char sm[];
    const uint32_t sb = smem_u32(sm);
    const int tid = threadIdx.x, lane = tid & 31, wid = tid >> 5;
    const int h = blockIdx.y, qt = blockIdx.x, half = blockIdx.z;
    const int grp = h * NQT + qt;

    const __nv_bfloat16* __restrict__ Qsrc = g_Q + ((size_t)h * NN + qt * 64) * YY;
    const __nv_bfloat16* __restrict__ Ksrc = g_K + (size_t)h * NN * YY
                                           + (size_t)half * (NN / KSPLIT) * YY;

    auto load_q = [&]() {
        #pragma unroll
        for (int i = 0; i < 4; i++) {
            int gi = tid + i * 128;
            int r = gi >> 3, c = gi & 7;
            cpa16(sb + r * ROWB + c * 16, Qsrc + (size_t)r * YY + c * 8);
        }
    };
    auto load_k = [&](int ch) {
        const int k0 = ch * 128;
        const uint32_t buf = sb + (ch & 1) * S_TILE;
        #pragma unroll
        for (int i = 0; i < 8; i++) {
            int gi = tid + i * 128;
            int r = gi >> 3, c = gi & 7;
            cpa16(buf + r * ROWB + c * 16, Ksrc + (size_t)(k0 + r) * YY + c * 8);
        }
    };

    const int lr = lane & 7;
    const uint32_t aoff = (uint32_t)((wid * 16 + lr + ((lane >> 3) & 1) * 8) * ROWB
                                     + ((lane >> 4) & 1) * 16);
    const uint32_t boff = (uint32_t)((lr + ((lane >> 4) & 1) * 8) * ROWB
                                     + ((lane >> 3) & 1) * 16);

    // Stage Q through buffer 0, pull fragments into registers, then free it.
    load_q(); CP_COMMIT(); CP_WAIT(0);
    __syncthreads();
    uint32_t aR[4][4];
    #pragma unroll
    for (int ks = 0; ks < 4; ks++)
        ldsm4(aR[ks][0], aR[ks][1], aR[ks][2], aR[ks][3], sb + aoff + ks * 32);
    __syncthreads();

    load_k(0); CP_COMMIT();

    float m0 = -INFINITY, l0 = 0.f;   // row a = wid*16 + (lane>>2)
    float m1 = -INFINITY, l1 = 0.f;   // row b = row a + 8

    auto upd = [](float v, float& m, float& l) {
        if (v > m) { l = l * __expf(m - v) + 1.0f; m = v; }
        else if (v > m - 16.0f) { l += __expf(v - m); }
    };

    for (int ch = 0; ch < KCH; ch++) {
        if (ch < KCH - 1) { load_k(ch + 1); CP_COMMIT(); CP_WAIT(1); }
        else CP_WAIT(0);
        __syncthreads();

        const uint32_t bbase = sb + (ch & 1) * S_TILE + boff;
        #pragma unroll
        for (int ntp = 0; ntp < 8; ntp++) {
            float acc[8];
            #pragma unroll
            for (int j = 0; j < 8; j++) acc[j] = 0.f;
            #pragma unroll
            for (int ks = 0; ks < 4; ks++) {
                uint32_t b0, b1, b2, b3;
                ldsm4(b0, b1, b2, b3, bbase + ntp * 16 * ROWB + ks * 32);
                mma16816(acc,     aR[ks], b0, b1);
                mma16816(acc + 4, aR[ks], b2, b3);
            }
            float ca = fmaxf(fmaxf(acc[0], acc[1]), fmaxf(acc[4], acc[5]));
            float cb = fmaxf(fmaxf(acc[2], acc[3]), fmaxf(acc[6], acc[7]));
            if (ca > m0 - 16.0f) {
                upd(acc[0], m0, l0); upd(acc[1], m0, l0);
                upd(acc[4], m0, l0); upd(acc[5], m0, l0);
            }
            if (cb > m1 - 16.0f) {
                upd(acc[2], m1, l1); upd(acc[3], m1, l1);
                upd(acc[6], m1, l1); upd(acc[7], m1, l1);
            }
        }
        __syncthreads();
    }

    // combine the 4 lanes of each quad-row (same row, disjoint k-cols)
    #pragma unroll
    for (int off = 1; off <= 2; off <<= 1) {
        float mo = __shfl_xor_sync(0xffffffffu, m0, off);
        float lo = __shfl_xor_sync(0xffffffffu, l0, off);
        float mm = fmaxf(m0, mo);
        l0 = l0 * __expf(m0 - mm) + lo * __expf(mo - mm);
        m0 = mm;
        mo = __shfl_xor_sync(0xffffffffu, m1, off);
        lo = __shfl_xor_sync(0xffffffffu, l1, off);
        mm = fmaxf(m1, mo);
        l1 = l1 * __expf(m1 - mm) + lo * __expf(mo - mm);
        m1 = mm;
    }

    // publish per-row (m,l) for this half
    float2* gml = g_ml + (size_t)grp * (KSPLIT * 64) + half * 64;
    if ((lane & 3) == 0) {
        int row = wid * 16 + (lane >> 2);
        gml[row]     = make_float2(m0, l0);
        gml[row + 8] = make_float2(m1, l1);
    }
    __threadfence();
    __syncthreads();

    __shared__ unsigned int pos;
    if (tid == 0) pos = atomicAdd(&g_ticket2[grp], 1u);
    __syncthreads();
    if (pos != KSPLIT - 1) return;

    // second finisher: merge halves (deterministic), row LSE, group sum
    float* red = reinterpret_cast<float*>(sm + S_RED);
    {
        float A = 0.f;
        if (tid < 64) {
            const float2* base = g_ml + (size_t)grp * (KSPLIT * 64);
            float2 a = __ldcg(&base[tid]);
            float2 b = __ldcg(&base[64 + tid]);
            float mm = fmaxf(a.x, b.x);
            float L = a.y * __expf(a.x - mm) + b.y * __expf(b.x - mm);
            A = mm + logf(L);
        }
        red[tid] = A;
        __syncthreads();
        if (tid < 32) {
            float s = red[tid] + red[tid + 32];
            #pragma unroll
            for (int off = 16; off > 0; off >>= 1)
                s += __shfl_xor_sync(0xffffffffu, s, off);
            if (tid == 0) g_partial[grp] = s;
        }
    }

    // global last-group election -> final deterministic sum of 384 partials
    __shared__ unsigned int is_last;
    __threadfence();
    if (tid == 0) is_last = (atomicAdd(&g_ticket, 1u) == NGRP - 1);
    __syncthreads();
    if (is_last) {
        __threadfence();
        float s = __ldcg(&g_partial[tid]) + __ldcg(&g_partial[tid + 128])
                + __ldcg(&g_partial[tid + 256]);
        red[tid] = s;
        __syncthreads();
        if (tid < 32) {
            float t = red[tid] + red[tid + 32] + red[tid + 64] + red[tid + 96];
            #pragma unroll
            for (int off = 16; off > 0; off >>= 1)
                t += __shfl_xor_sync(0xffffffffu, t, off);
            if (tid == 0) out[0] = -8.0f * t;
        }
    }
}

extern "C" void kernel_launch(void* const* d_in, const int* in_sizes, int n_in,
                              void* d_out, int out_size)
{
    (void)in_sizes; (void)n_in; (void)out_size;
    const float* g  = (const float*)d_in[0];
    const float* Wq = (const float*)d_in[1];
    const float* Wk = (const float*)d_in[2];
    float* out = (float*)d_out;

    conv_kernel<<<(CONV_T + 255) / 256, 256>>>(g, Wq, Wk);
    proj_kernel<<<dim3(6, 32, 2), 128, P_SMEM>>>();
    scores_kernel<<<dim3(NQT, HH, KSPLIT), 128, S_SMEM>>>(out);
}

// round 13
// speedup vs baseline: 1.7166x; 1.2171x over previous
#include <cuda_runtime.h>
#include <cuda_bf16.h>
#include <cstdint>
#include <math.h>

#define NN 2048
#define DD 768
#define HH 12
#define YY 64

#define NQT 32                 // q-tiles per head (qtile = 64 rows)
#define NGRP (HH * NQT)        // 384 (h, qt) groups
#define KSPLIT 2               // K-range halves per group
#define KCH (NN / KSPLIT / 128)// 8 chunks of 128 per CTA

// ---------------------------------------------------------------------------
// Scratch (__device__ globals; no allocation allowed)
// ---------------------------------------------------------------------------
__device__ __nv_bfloat16 g_gb [NN * DD];       // g in bf16
__device__ __nv_bfloat16 g_Wqb[HH * YY * DD];  // Wq in bf16
__device__ __nv_bfloat16 g_Wkb[HH * YY * DD];  // Wk in bf16
__device__ __nv_bfloat16 g_Q[HH * NN * YY];    // [h][n][y], pre-scaled by beta
__device__ __nv_bfloat16 g_K[HH * NN * YY];    // [h][n][y]
__device__ float2 g_ml[NGRP * KSPLIT * 64];    // per-row (m,l) per half
__device__ float g_partial[NGRP];              // per-group LSE row sums
__device__ unsigned int g_ticket2[NGRP];       // per-group pair election
__device__ unsigned int g_ticket;              // global last-group election

// ---------------------------------------------------------------------------
// Helpers (standard sm_80+ features: ldmatrix / mma.sync / cp.async)
// ---------------------------------------------------------------------------
__device__ __forceinline__ uint32_t smem_u32(const void* p) {
    uint32_t a;
    asm("{ .reg .u64 t; cvta.to.shared.u64 t, %1; cvt.u32.u64 %0, t; }" : "=r"(a) : "l"(p));
    return a;
}

__device__ __forceinline__ void cpa16(uint32_t dst, const void* src) {
    asm volatile("cp.async.cg.shared.global [%0], [%1], 16;" :: "r"(dst), "l"(src));
}
#define CP_COMMIT() asm volatile("cp.async.commit_group;" ::: "memory")
#define CP_WAIT(n)  asm volatile("cp.async.wait_group %0;" :: "n"(n) : "memory")

__device__ __forceinline__ void ldsm4(uint32_t& r0, uint32_t& r1, uint32_t& r2, uint32_t& r3,
                                      uint32_t addr) {
    asm volatile("ldmatrix.sync.aligned.m8n8.x4.shared.b16 {%0,%1,%2,%3}, [%4];"
                 : "=r"(r0), "=r"(r1), "=r"(r2), "=r"(r3) : "r"(addr));
}

__device__ __forceinline__ void mma16816(float* c, const uint32_t* a, uint32_t b0, uint32_t b1) {
    asm volatile(
        "mma.sync.aligned.m16n8k16.row.col.f32.bf16.bf16.f32 "
        "{%0,%1,%2,%3}, {%4,%5,%6,%7}, {%8,%9}, {%0,%1,%2,%3};"
        : "+f"(c[0]), "+f"(c[1]), "+f"(c[2]), "+f"(c[3])
        : "r"(a[0]), "r"(a[1]), "r"(a[2]), "r"(a[3]), "r"(b0), "r"(b1));
}

__device__ __forceinline__ uint32_t bf16x2(float hi, float lo) {
    uint32_t r;
    asm("cvt.rn.bf16x2.f32 %0, %1, %2;" : "=r"(r) : "f"(hi), "f"(lo));
    return r;
}

// ---------------------------------------------------------------------------
// Convert f32 inputs -> bf16 globals; reset tickets. (R8 version: max TLP)
// ---------------------------------------------------------------------------
#define NG8 (NN * DD / 8)          // 196608
#define NW8 (HH * YY * DD / 8)     // 73728

__global__ void __launch_bounds__(256) conv_kernel(const float* __restrict__ g,
                                                   const float* __restrict__ wq,
                                                   const float* __restrict__ wk)
{
    int i = blockIdx.x * 256 + threadIdx.x;
    if (i == 0) g_ticket = 0;
    if (i < NGRP) g_ticket2[i] = 0;
    const float* src;
    __nv_bfloat16* dst;
    int j;
    if (i < NG8)                { src = g;  dst = g_gb;  j = i; }
    else if (i < NG8 + NW8)     { src = wq; dst = g_Wqb; j = i - NG8; }
    else if (i < NG8 + 2 * NW8) { src = wk; dst = g_Wkb; j = i - NG8 - NW8; }
    else return;
    float4 v0 = *reinterpret_cast<const float4*>(src + (size_t)j * 8);
    float4 v1 = *reinterpret_cast<const float4*>(src + (size_t)j * 8 + 4);
    uint4 o;
    o.x = bf16x2(v0.y, v0.x);
    o.y = bf16x2(v0.w, v0.z);
    o.z = bf16x2(v1.y, v1.x);
    o.w = bf16x2(v1.w, v1.z);
    *reinterpret_cast<uint4*>(dst + (size_t)j * 8) = o;
}

// ---------------------------------------------------------------------------
// Projection: Out[c][n] for c = h*64+y.  Out = g . W^T.   (R8 version)
// CTA tile 64n x 128c, 128 threads (4 warps: 2m x 2n, warp tile 32x64).
// k-chunk 32 (pitch 80B). grid (6, 32, 2) = 384 CTAs.
// ---------------------------------------------------------------------------
#define PROWB 80
#define PA_TILE (64 * PROWB)                // 5120 B
#define PB_TILE (128 * PROWB)               // 10240 B
#define P_STAGE (PA_TILE + PB_TILE)         // 15360 B
#define P_SMEM (2 * P_STAGE)                // 30720 B

__global__ void __launch_bounds__(128) proj_kernel()
{
    extern __shared__ char sm[];
    const uint32_t sb = smem_u32(sm);
    const int tid = threadIdx.x, lane = tid & 31, wid = tid >> 5;
    const int wm = wid & 1, wn = wid >> 1;
    const int c0 = blockIdx.x * 128, n0 = blockIdx.y * 64;
    const __nv_bfloat16* __restrict__ A = g_gb;
    const __nv_bfloat16* __restrict__ B = blockIdx.z ? g_Wkb : g_Wqb;
    __nv_bfloat16* __restrict__ Out = blockIdx.z ? g_K : g_Q;
    const float scale = blockIdx.z ? 1.0f : 0.125f;

    auto load_chunk = [&](int ch) {
        const int d0 = ch * 32;
        const uint32_t abuf = sb + (ch & 1) * P_STAGE;
        const uint32_t bbuf = abuf + PA_TILE;
        #pragma unroll
        for (int i = 0; i < 2; i++) {
            int gi = tid + i * 128;
            int r = gi >> 2, c = gi & 3;
            cpa16(abuf + r * PROWB + c * 16, A + (size_t)(n0 + r) * DD + d0 + c * 8);
        }
        #pragma unroll
        for (int i = 0; i < 4; i++) {
            int gi = tid + i * 128;
            int r = gi >> 2, c = gi & 3;
            cpa16(bbuf + r * PROWB + c * 16, B + (size_t)(c0 + r) * DD + d0 + c * 8);
        }
    };

    float acc[2][8][4];
    #pragma unroll
    for (int mt = 0; mt < 2; mt++)
        #pragma unroll
        for (int nt = 0; nt < 8; nt++)
            #pragma unroll
            for (int k = 0; k < 4; k++) acc[mt][nt][k] = 0.f;

    const int lr = lane & 7;
    const uint32_t aoff = (uint32_t)((wm * 32 + lr + ((lane >> 3) & 1) * 8) * PROWB
                                     + ((lane >> 4) & 1) * 16);
    const uint32_t boff = (uint32_t)((wn * 64 + lr + ((lane >> 4) & 1) * 8) * PROWB
                                     + ((lane >> 3) & 1) * 16);

    load_chunk(0); CP_COMMIT();

    for (int ch = 0; ch < 24; ch++) {
        if (ch < 23) { load_chunk(ch + 1); CP_COMMIT(); CP_WAIT(1); }
        else CP_WAIT(0);
        __syncthreads();

        const uint32_t abase = sb + (ch & 1) * P_STAGE + aoff;
        const uint32_t bbase = sb + (ch & 1) * P_STAGE + PA_TILE + boff;
        #pragma unroll
        for (int ks = 0; ks < 2; ks++) {
            uint32_t a0[4], a1[4];
            ldsm4(a0[0], a0[1], a0[2], a0[3], abase + ks * 32);
            ldsm4(a1[0], a1[1], a1[2], a1[3], abase + 16 * PROWB + ks * 32);
            #pragma unroll
            for (int ntp = 0; ntp < 4; ntp++) {
                uint32_t b0, b1, b2, b3;
                ldsm4(b0, b1, b2, b3, bbase + ntp * 16 * PROWB + ks * 32);
                mma16816(acc[0][2 * ntp],     a0, b0, b1);
                mma16816(acc[1][2 * ntp],     a1, b0, b1);
                mma16816(acc[0][2 * ntp + 1], a0, b2, b3);
                mma16816(acc[1][2 * ntp + 1], a1, b2, b3);
            }
        }
        __syncthreads();
    }

    const int h = (c0 >> 6) + wn;
    const int rbase = n0 + wm * 32 + (lane >> 2);
    #pragma unroll
    for (int mt = 0; mt < 2; mt++) {
        #pragma unroll
        for (int nt = 0; nt < 8; nt++) {
            const int y = nt * 8 + (lane & 3) * 2;
            const int n1 = rbase + mt * 16;
            uint32_t p0 = bf16x2(acc[mt][nt][1] * scale, acc[mt][nt][0] * scale);
            uint32_t p1 = bf16x2(acc[mt][nt][3] * scale, acc[mt][nt][2] * scale);
            *reinterpret_cast<uint32_t*>(&Out[((size_t)h * NN + n1) * YY + y])     = p0;
            *reinterpret_cast<uint32_t*>(&Out[((size_t)h * NN + n1 + 8) * YY + y]) = p1;
        }
    }
}

// ---------------------------------------------------------------------------
// Fused scores + LSE, split-K (KSPLIT=2). CTA per (qtile 64, head, K-half).
// 4 warps x 16 q-rows, 8 K-chunks per CTA. Flattened branchless-triggered
// online LSE: one branch per row-group; inside, all 4 exps unconditional.
// grid (32, 12, 2) = 768 CTAs of 128 threads.
// ---------------------------------------------------------------------------
#define ROWB 144
#define S_TILE (128 * ROWB)                 // 18432 B
#define S_RED  (2 * S_TILE)
#define S_SMEM (S_RED + 128 * 4)            // 37376 B

__global__ void __launch_bounds__(128) scores_kernel(float* __restrict__ out)
{
    extern __shared__ char sm[];
    const uint32_t sb = smem_u32(sm);
    const int tid = threadIdx.x, lane = tid & 31, wid = tid >> 5;
    const int h = blockIdx.y, qt = blockIdx.x, half = blockIdx.z;
    const int grp = h * NQT + qt;

    const __nv_bfloat16* __restrict__ Qsrc = g_Q + ((size_t)h * NN + qt * 64) * YY;
    const __nv_bfloat16* __restrict__ Ksrc = g_K + (size_t)h * NN * YY
                                           + (size_t)half * (NN / KSPLIT) * YY;

    auto load_q = [&]() {
        #pragma unroll
        for (int i = 0; i < 4; i++) {
            int gi = tid + i * 128;
            int r = gi >> 3, c = gi & 7;
            cpa16(sb + r * ROWB + c * 16, Qsrc + (size_t)r * YY + c * 8);
        }
    };
    auto load_k = [&](int ch) {
        const int k0 = ch * 128;
        const uint32_t buf = sb + (ch & 1) * S_TILE;
        #pragma unroll
        for (int i = 0; i < 8; i++) {
            int gi = tid + i * 128;
            int r = gi >> 3, c = gi & 7;
            cpa16(buf + r * ROWB + c * 16, Ksrc + (size_t)(k0 + r) * YY + c * 8);
        }
    };

    const int lr = lane & 7;
    const uint32_t aoff = (uint32_t)((wid * 16 + lr + ((lane >> 3) & 1) * 8) * ROWB
                                     + ((lane >> 4) & 1) * 16);
    const uint32_t boff = (uint32_t)((lr + ((lane >> 4) & 1) * 8) * ROWB
                                     + ((lane >> 3) & 1) * 16);

    // Stage Q through buffer 0, pull fragments into registers, then free it.
    load_q(); CP_COMMIT(); CP_WAIT(0);
    __syncthreads();
    uint32_t aR[4][4];
    #pragma unroll
    for (int ks = 0; ks < 4; ks++)
        ldsm4(aR[ks][0], aR[ks][1], aR[ks][2], aR[ks][3], sb + aoff + ks * 32);
    __syncthreads();

    load_k(0); CP_COMMIT();

    float m0 = -INFINITY, l0 = 0.f;   // row a = wid*16 + (lane>>2)
    float m1 = -INFINITY, l1 = 0.f;   // row b = row a + 8

    for (int ch = 0; ch < KCH; ch++) {
        if (ch < KCH - 1) { load_k(ch + 1); CP_COMMIT(); CP_WAIT(1); }
        else CP_WAIT(0);
        __syncthreads();

        const uint32_t bbase = sb + (ch & 1) * S_TILE + boff;
        #pragma unroll
        for (int ntp = 0; ntp < 8; ntp++) {
            float acc[8];
            #pragma unroll
            for (int j = 0; j < 8; j++) acc[j] = 0.f;
            #pragma unroll
            for (int ks = 0; ks < 4; ks++) {
                uint32_t b0, b1, b2, b3;
                ldsm4(b0, b1, b2, b3, bbase + ntp * 16 * ROWB + ks * 32);
                mma16816(acc,     aR[ks], b0, b1);
                mma16816(acc + 4, aR[ks], b2, b3);
            }
            // rows: acc[0],[1],[4],[5] -> row a ; acc[2],[3],[6],[7] -> row b
            float ca = fmaxf(fmaxf(acc[0], acc[1]), fmaxf(acc[4], acc[5]));
            float cb = fmaxf(fmaxf(acc[2], acc[3]), fmaxf(acc[6], acc[7]));
            if (ca > m0 - 16.0f) {        // flat triggered path, no inner branches
                float mn = fmaxf(m0, ca);
                l0 = l0 * __expf(m0 - mn)
                   + __expf(acc[0] - mn) + __expf(acc[1] - mn)
                   + __expf(acc[4] - mn) + __expf(acc[5] - mn);
                m0 = mn;
            }
            if (cb > m1 - 16.0f) {
                float mn = fmaxf(m1, cb);
                l1 = l1 * __expf(m1 - mn)
                   + __expf(acc[2] - mn) + __expf(acc[3] - mn)
                   + __expf(acc[6] - mn) + __expf(acc[7] - mn);
                m1 = mn;
            }
        }
        __syncthreads();
    }

    // combine the 4 lanes of each quad-row (same row, disjoint k-cols)
    #pragma unroll
    for (int off = 1; off <= 2; off <<= 1) {
        float mo = __shfl_xor_sync(0xffffffffu, m0, off);
        float lo = __shfl_xor_sync(0xffffffffu, l0, off);
        float mm = fmaxf(m0, mo);
        l0 = l0 * __expf(m0 - mm) + lo * __expf(mo - mm);
        m0 = mm;
        mo = __shfl_xor_sync(0xffffffffu, m1, off);
        lo = __shfl_xor_sync(0xffffffffu, l1, off);
        mm = fmaxf(m1, mo);
        l1 = l1 * __expf(m1 - mm) + lo * __expf(mo - mm);
        m1 = mm;
    }

    // publish per-row (m,l) for this half
    float2* gml = g_ml + (size_t)grp * (KSPLIT * 64) + half * 64;
    if ((lane & 3) == 0) {
        int row = wid * 16 + (lane >> 2);
        gml[row]     = make_float2(m0, l0);
        gml[row + 8] = make_float2(m1, l1);
    }
    __threadfence();
    __syncthreads();

    __shared__ unsigned int pos;
    if (tid == 0) pos = atomicAdd(&g_ticket2[grp], 1u);
    __syncthreads();
    if (pos != KSPLIT - 1) return;

    // second finisher: merge halves (deterministic), row LSE, group sum
    float* red = reinterpret_cast<float*>(sm + S_RED);
    {
        float A = 0.f;
        if (tid < 64) {
            const float2* base = g_ml + (size_t)grp * (KSPLIT * 64);
            float2 a = __ldcg(&base[tid]);
            float2 b = __ldcg(&base[64 + tid]);
            float mm = fmaxf(a.x, b.x);
            float L = a.y * __expf(a.x - mm) + b.y * __expf(b.x - mm);
            A = mm + logf(L);
        }
        red[tid] = A;
        __syncthreads();
        if (tid < 32) {
            float s = red[tid] + red[tid + 32];
            #pragma unroll
            for (int off = 16; off > 0; off >>= 1)
                s += __shfl_xor_sync(0xffffffffu, s, off);
            if (tid == 0) g_partial[grp] = s;
        }
    }

    // global last-group election -> final deterministic sum of 384 partials
    __shared__ unsigned int is_last;
    __threadfence();
    if (tid == 0) is_last = (atomicAdd(&g_ticket, 1u) == NGRP - 1);
    __syncthreads();
    if (is_last) {
        __threadfence();
        float s = __ldcg(&g_partial[tid]) + __ldcg(&g_partial[tid + 128])
                + __ldcg(&g_partial[tid + 256]);
        red[tid] = s;
        __syncthreads();
        if (tid < 32) {
            float t = red[tid] + red[tid + 32] + red[tid + 64] + red[tid + 96];
            #pragma unroll
            for (int off = 16; off > 0; off >>= 1)
                t += __shfl_xor_sync(0xffffffffu, t, off);
            if (tid == 0) out[0] = -8.0f * t;
        }
    }
}

extern "C" void kernel_launch(void* const* d_in, const int* in_sizes, int n_in,
                              void* d_out, int out_size)
{
    (void)in_sizes; (void)n_in; (void)out_size;
    const float* g  = (const float*)d_in[0];
    const float* Wq = (const float*)d_in[1];
    const float* Wk = (const float*)d_in[2];
    float* out = (float*)d_out;

    const int convN = NG8 + 2 * NW8;
    conv_kernel<<<(convN + 255) / 256, 256>>>(g, Wq, Wk);
    proj_kernel<<<dim3(6, 32, 2), 128, P_SMEM>>>();
    scores_kernel<<<dim3(NQT, HH, KSPLIT), 128, S_SMEM>>>(out);
}

// round 14
// speedup vs baseline: 1.7174x; 1.0005x over previous
#include <cuda_runtime.h>
#include <cuda_bf16.h>
#include <cstdint>
#include <math.h>

#define NN 2048
#define DD 768
#define HH 12
#define YY 64

#define NQT 32                 // q-tiles per head (qtile = 64 rows)
#define NGRP (HH * NQT)        // 384 (h, qt) groups
#define KSPLIT 2               // K-range halves per group
#define KCH (NN / KSPLIT / 128)// 8 chunks of 128 per CTA

// ---------------------------------------------------------------------------
// Scratch (__device__ globals; no allocation allowed)
// ---------------------------------------------------------------------------
__device__ __nv_bfloat16 g_gb [NN * DD];       // g in bf16
__device__ __nv_bfloat16 g_Wqb[HH * YY * DD];  // Wq in bf16
__device__ __nv_bfloat16 g_Wkb[HH * YY * DD];  // Wk in bf16
__device__ __nv_bfloat16 g_Q[HH * NN * YY];    // [h][n][y], pre-scaled by beta
__device__ __nv_bfloat16 g_K[HH * NN * YY];    // [h][n][y]
__device__ float2 g_ml[NGRP * KSPLIT * 64];    // per-row (m,l) per half
__device__ float g_partial[NGRP];              // per-group LSE row sums
__device__ unsigned int g_ticket2[NGRP];       // per-group pair election
__device__ unsigned int g_ticket;              // global last-group election

// ---------------------------------------------------------------------------
// Helpers (standard sm_80+ features: ldmatrix / mma.sync / cp.async)
// ---------------------------------------------------------------------------
__device__ __forceinline__ uint32_t smem_u32(const void* p) {
    uint32_t a;
    asm("{ .reg .u64 t; cvta.to.shared.u64 t, %1; cvt.u32.u64 %0, t; }" : "=r"(a) : "l"(p));
    return a;
}

__device__ __forceinline__ void cpa16(uint32_t dst, const void* src) {
    asm volatile("cp.async.cg.shared.global [%0], [%1], 16;" :: "r"(dst), "l"(src));
}
#define CP_COMMIT() asm volatile("cp.async.commit_group;" ::: "memory")
#define CP_WAIT(n)  asm volatile("cp.async.wait_group %0;" :: "n"(n) : "memory")

__device__ __forceinline__ void ldsm4(uint32_t& r0, uint32_t& r1, uint32_t& r2, uint32_t& r3,
                                      uint32_t addr) {
    asm volatile("ldmatrix.sync.aligned.m8n8.x4.shared.b16 {%0,%1,%2,%3}, [%4];"
                 : "=r"(r0), "=r"(r1), "=r"(r2), "=r"(r3) : "r"(addr));
}

__device__ __forceinline__ void mma16816(float* c, const uint32_t* a, uint32_t b0, uint32_t b1) {
    asm volatile(
        "mma.sync.aligned.m16n8k16.row.col.f32.bf16.bf16.f32 "
        "{%0,%1,%2,%3}, {%4,%5,%6,%7}, {%8,%9}, {%0,%1,%2,%3};"
        : "+f"(c[0]), "+f"(c[1]), "+f"(c[2]), "+f"(c[3])
        : "r"(a[0]), "r"(a[1]), "r"(a[2]), "r"(a[3]), "r"(b0), "r"(b1));
}

__device__ __forceinline__ uint32_t bf16x2(float hi, float lo) {
    uint32_t r;
    asm("cvt.rn.bf16x2.f32 %0, %1, %2;" : "=r"(r) : "f"(hi), "f"(lo));
    return r;
}

// ---------------------------------------------------------------------------
// Convert f32 inputs -> bf16 globals; reset tickets. (R8 version: max TLP)
// ---------------------------------------------------------------------------
#define NG8 (NN * DD / 8)          // 196608
#define NW8 (HH * YY * DD / 8)     // 73728

__global__ void __launch_bounds__(256) conv_kernel(const float* __restrict__ g,
                                                   const float* __restrict__ wq,
                                                   const float* __restrict__ wk)
{
    int i = blockIdx.x * 256 + threadIdx.x;
    if (i == 0) g_ticket = 0;
    if (i < NGRP) g_ticket2[i] = 0;
    const float* src;
    __nv_bfloat16* dst;
    int j;
    if (i < NG8)                { src = g;  dst = g_gb;  j = i; }
    else if (i < NG8 + NW8)     { src = wq; dst = g_Wqb; j = i - NG8; }
    else if (i < NG8 + 2 * NW8) { src = wk; dst = g_Wkb; j = i - NG8 - NW8; }
    else return;
    float4 v0 = *reinterpret_cast<const float4*>(src + (size_t)j * 8);
    float4 v1 = *reinterpret_cast<const float4*>(src + (size_t)j * 8 + 4);
    uint4 o;
    o.x = bf16x2(v0.y, v0.x);
    o.y = bf16x2(v0.w, v0.z);
    o.z = bf16x2(v1.y, v1.x);
    o.w = bf16x2(v1.w, v1.z);
    *reinterpret_cast<uint4*>(dst + (size_t)j * 8) = o;
}

// ---------------------------------------------------------------------------
// Projection: Out[c][n] for c = h*64+y.  Out = g . W^T.
// CTA tile 64n x 128c, 128 threads (4 warps: 2m x 2n, warp tile 32x64).
// 3-stage cp.async pipeline, ONE __syncthreads per k-chunk.
// grid (6, 32, 2) = 384 CTAs. Dynamic smem: 3*15360 = 46080 B (< 48KB).
// ---------------------------------------------------------------------------
#define PROWB 80
#define PA_TILE (64 * PROWB)                // 5120 B
#define PB_TILE (128 * PROWB)               // 10240 B
#define P_STAGE (PA_TILE + PB_TILE)         // 15360 B
#define P_SMEM (3 * P_STAGE)                // 46080 B

__global__ void __launch_bounds__(128) proj_kernel()
{
    extern __shared__ char sm[];
    const uint32_t sb = smem_u32(sm);
    const int tid = threadIdx.x, lane = tid & 31, wid = tid >> 5;
    const int wm = wid & 1, wn = wid >> 1;
    const int c0 = blockIdx.x * 128, n0 = blockIdx.y * 64;
    const __nv_bfloat16* __restrict__ A = g_gb;
    const __nv_bfloat16* __restrict__ B = blockIdx.z ? g_Wkb : g_Wqb;
    __nv_bfloat16* __restrict__ Out = blockIdx.z ? g_K : g_Q;
    const float scale = blockIdx.z ? 1.0f : 0.125f;

    auto load_chunk = [&](int ch, int st) {
        const int d0 = ch * 32;
        const uint32_t abuf = sb + st * P_STAGE;
        const uint32_t bbuf = abuf + PA_TILE;
        #pragma unroll
        for (int i = 0; i < 2; i++) {
            int gi = tid + i * 128;
            int r = gi >> 2, c = gi & 3;
            cpa16(abuf + r * PROWB + c * 16, A + (size_t)(n0 + r) * DD + d0 + c * 8);
        }
        #pragma unroll
        for (int i = 0; i < 4; i++) {
            int gi = tid + i * 128;
            int r = gi >> 2, c = gi & 3;
            cpa16(bbuf + r * PROWB + c * 16, B + (size_t)(c0 + r) * DD + d0 + c * 8);
        }
    };

    float acc[2][8][4];
    #pragma unroll
    for (int mt = 0; mt < 2; mt++)
        #pragma unroll
        for (int nt = 0; nt < 8; nt++)
            #pragma unroll
            for (int k = 0; k < 4; k++) acc[mt][nt][k] = 0.f;

    const int lr = lane & 7;
    const uint32_t aoff = (uint32_t)((wm * 32 + lr + ((lane >> 3) & 1) * 8) * PROWB
                                     + ((lane >> 4) & 1) * 16);
    const uint32_t boff = (uint32_t)((wn * 64 + lr + ((lane >> 4) & 1) * 8) * PROWB
                                     + ((lane >> 3) & 1) * 16);

    load_chunk(0, 0); CP_COMMIT();
    load_chunk(1, 1); CP_COMMIT();

    int rst = 0, wst = 2;
    for (int ch = 0; ch < 24; ch++) {
        if (ch < 23) CP_WAIT(1); else CP_WAIT(0);
        __syncthreads();

        const uint32_t stage = sb + rst * P_STAGE;
        const uint32_t abase = stage + aoff;
        const uint32_t bbase = stage + PA_TILE + boff;
        #pragma unroll
        for (int ks = 0; ks < 2; ks++) {
            uint32_t a0[4], a1[4];
            ldsm4(a0[0], a0[1], a0[2], a0[3], abase + ks * 32);
            ldsm4(a1[0], a1[1], a1[2], a1[3], abase + 16 * PROWB + ks * 32);
            #pragma unroll
            for (int ntp = 0; ntp < 4; ntp++) {
                uint32_t b0, b1, b2, b3;
                ldsm4(b0, b1, b2, b3, bbase + ntp * 16 * PROWB + ks * 32);
                mma16816(acc[0][2 * ntp],     a0, b0, b1);
                mma16816(acc[1][2 * ntp],     a1, b0, b1);
                mma16816(acc[0][2 * ntp + 1], a0, b2, b3);
                mma16816(acc[1][2 * ntp + 1], a1, b2, b3);
            }
        }
        if (ch < 22) { load_chunk(ch + 2, wst); CP_COMMIT(); }
        rst = (rst == 2) ? 0 : rst + 1;
        wst = (wst == 2) ? 0 : wst + 1;
    }

    const int h = (c0 >> 6) + wn;
    const int rbase = n0 + wm * 32 + (lane >> 2);
    #pragma unroll
    for (int mt = 0; mt < 2; mt++) {
        #pragma unroll
        for (int nt = 0; nt < 8; nt++) {
            const int y = nt * 8 + (lane & 3) * 2;
            const int n1 = rbase + mt * 16;
            uint32_t p0 = bf16x2(acc[mt][nt][1] * scale, acc[mt][nt][0] * scale);
            uint32_t p1 = bf16x2(acc[mt][nt][3] * scale, acc[mt][nt][2] * scale);
            *reinterpret_cast<uint32_t*>(&Out[((size_t)h * NN + n1) * YY + y])     = p0;
            *reinterpret_cast<uint32_t*>(&Out[((size_t)h * NN + n1 + 8) * YY + y]) = p1;
        }
    }
}

// ---------------------------------------------------------------------------
// Fused scores + LSE, split-K (KSPLIT=2). CTA per (qtile 64, head, K-half).
// 4 warps x 16 q-rows, 8 K-chunks per CTA. Flattened branchless-triggered
// online LSE. grid (32, 12, 2) = 768 CTAs of 128 threads.  (R13 version)
// ---------------------------------------------------------------------------
#define ROWB 144
#define S_TILE (128 * ROWB)                 // 18432 B
#define S_RED  (2 * S_TILE)
#define S_SMEM (S_RED + 128 * 4)            // 37376 B

__global__ void __launch_bounds__(128) scores_kernel(float* __restrict__ out)
{
    extern __shared__ char sm[];
    const uint32_t sb = smem_u32(sm);
    const int tid = threadIdx.x, lane = tid & 31, wid = tid >> 5;
    const int h = blockIdx.y, qt = blockIdx.x, half = blockIdx.z;
    const int grp = h * NQT + qt;

    const __nv_bfloat16* __restrict__ Qsrc = g_Q + ((size_t)h * NN + qt * 64) * YY;
    const __nv_bfloat16* __restrict__ Ksrc = g_K + (size_t)h * NN * YY
                                           + (size_t)half * (NN / KSPLIT) * YY;

    auto load_q = [&]() {
        #pragma unroll
        for (int i = 0; i < 4; i++) {
            int gi = tid + i * 128;
            int r = gi >> 3, c = gi & 7;
            cpa16(sb + r * ROWB + c * 16, Qsrc + (size_t)r * YY + c * 8);
        }
    };
    auto load_k = [&](int ch) {
        const int k0 = ch * 128;
        const uint32_t buf = sb + (ch & 1) * S_TILE;
        #pragma unroll
        for (int i = 0; i < 8; i++) {
            int gi = tid + i * 128;
            int r = gi >> 3, c = gi & 7;
            cpa16(buf + r * ROWB + c * 16, Ksrc + (size_t)(k0 + r) * YY + c * 8);
        }
    };

    const int lr = lane & 7;
    const uint32_t aoff = (uint32_t)((wid * 16 + lr + ((lane >> 3) & 1) * 8) * ROWB
                                     + ((lane >> 4) & 1) * 16);
    const uint32_t boff = (uint32_t)((lr + ((lane >> 4) & 1) * 8) * ROWB
                                     + ((lane >> 3) & 1) * 16);

    // Stage Q through buffer 0, pull fragments into registers, then free it.
    load_q(); CP_COMMIT(); CP_WAIT(0);
    __syncthreads();
    uint32_t aR[4][4];
    #pragma unroll
    for (int ks = 0; ks < 4; ks++)
        ldsm4(aR[ks][0], aR[ks][1], aR[ks][2], aR[ks][3], sb + aoff + ks * 32);
    __syncthreads();

    load_k(0); CP_COMMIT();

    float m0 = -INFINITY, l0 = 0.f;   // row a = wid*16 + (lane>>2)
    float m1 = -INFINITY, l1 = 0.f;   // row b = row a + 8

    for (int ch = 0; ch < KCH; ch++) {
        if (ch < KCH - 1) { load_k(ch + 1); CP_COMMIT(); CP_WAIT(1); }
        else CP_WAIT(0);
        __syncthreads();

        const uint32_t bbase = sb + (ch & 1) * S_TILE + boff;
        #pragma unroll
        for (int ntp = 0; ntp < 8; ntp++) {
            float acc[8];
            #pragma unroll
            for (int j = 0; j < 8; j++) acc[j] = 0.f;
            #pragma unroll
            for (int ks = 0; ks < 4; ks++) {
                uint32_t b0, b1, b2, b3;
                ldsm4(b0, b1, b2, b3, bbase + ntp * 16 * ROWB + ks * 32);
                mma16816(acc,     aR[ks], b0, b1);
                mma16816(acc + 4, aR[ks], b2, b3);
            }
            // rows: acc[0],[1],[4],[5] -> row a ; acc[2],[3],[6],[7] -> row b
            float ca = fmaxf(fmaxf(acc[0], acc[1]), fmaxf(acc[4], acc[5]));
            float cb = fmaxf(fmaxf(acc[2], acc[3]), fmaxf(acc[6], acc[7]));
            if (ca > m0 - 16.0f) {        // flat triggered path, no inner branches
                float mn = fmaxf(m0, ca);
                l0 = l0 * __expf(m0 - mn)
                   + __expf(acc[0] - mn) + __expf(acc[1] - mn)
                   + __expf(acc[4] - mn) + __expf(acc[5] - mn);
                m0 = mn;
            }
            if (cb > m1 - 16.0f) {
                float mn = fmaxf(m1, cb);
                l1 = l1 * __expf(m1 - mn)
                   + __expf(acc[2] - mn) + __expf(acc[3] - mn)
                   + __expf(acc[6] - mn) + __expf(acc[7] - mn);
                m1 = mn;
            }
        }
        __syncthreads();
    }

    // combine the 4 lanes of each quad-row (same row, disjoint k-cols)
    #pragma unroll
    for (int off = 1; off <= 2; off <<= 1) {
        float mo = __shfl_xor_sync(0xffffffffu, m0, off);
        float lo = __shfl_xor_sync(0xffffffffu, l0, off);
        float mm = fmaxf(m0, mo);
        l0 = l0 * __expf(m0 - mm) + lo * __expf(mo - mm);
        m0 = mm;
        mo = __shfl_xor_sync(0xffffffffu, m1, off);
        lo = __shfl_xor_sync(0xffffffffu, l1, off);
        mm = fmaxf(m1, mo);
        l1 = l1 * __expf(m1 - mm) + lo * __expf(mo - mm);
        m1 = mm;
    }

    // publish per-row (m,l) for this half
    float2* gml = g_ml + (size_t)grp * (KSPLIT * 64) + half * 64;
    if ((lane & 3) == 0) {
        int row = wid * 16 + (lane >> 2);
        gml[row]     = make_float2(m0, l0);
        gml[row + 8] = make_float2(m1, l1);
    }
    __threadfence();
    __syncthreads();

    __shared__ unsigned int pos;
    if (tid == 0) pos = atomicAdd(&g_ticket2[grp], 1u);
    __syncthreads();
    if (pos != KSPLIT - 1) return;

    // second finisher: merge halves (deterministic), row LSE, group sum
    float* red = reinterpret_cast<float*>(sm + S_RED);
    {
        float A = 0.f;
        if (tid < 64) {
            const float2* base = g_ml + (size_t)grp * (KSPLIT * 64);
            float2 a = __ldcg(&base[tid]);
            float2 b = __ldcg(&base[64 + tid]);
            float mm = fmaxf(a.x, b.x);
            float L = a.y * __expf(a.x - mm) + b.y * __expf(b.x - mm);
            A = mm + logf(L);
        }
        red[tid] = A;
        __syncthreads();
        if (tid < 32) {
            float s = red[tid] + red[tid + 32];
            #pragma unroll
            for (int off = 16; off > 0; off >>= 1)
                s += __shfl_xor_sync(0xffffffffu, s, off);
            if (tid == 0) g_partial[grp] = s;
        }
    }

    // global last-group election -> final deterministic sum of 384 partials
    __shared__ unsigned int is_last;
    __threadfence();
    if (tid == 0) is_last = (atomicAdd(&g_ticket, 1u) == NGRP - 1);
    __syncthreads();
    if (is_last) {
        __threadfence();
        float s = __ldcg(&g_partial[tid]) + __ldcg(&g_partial[tid + 128])
                + __ldcg(&g_partial[tid + 256]);
        red[tid] = s;
        __syncthreads();
        if (tid < 32) {
            float t = red[tid] + red[tid + 32] + red[tid + 64] + red[tid + 96];
            #pragma unroll
            for (int off = 16; off > 0; off >>= 1)
                t += __shfl_xor_sync(0xffffffffu, t, off);
            if (tid == 0) out[0] = -8.0f * t;
        }
    }
}

extern "C" void kernel_launch(void* const* d_in, const int* in_sizes, int n_in,
                              void* d_out, int out_size)
{
    (void)in_sizes; (void)n_in; (void)out_size;
    const float* g  = (const float*)d_in[0];
    const float* Wq = (const float*)d_in[1];
    const float* Wk = (const float*)d_in[2];
    float* out = (float*)d_out;

    const int convN = NG8 + 2 * NW8;
    conv_kernel<<<(convN + 255) / 256, 256>>>(g, Wq, Wk);
    proj_kernel<<<dim3(6, 32, 2), 128, P_SMEM>>>();
    scores_kernel<<<dim3(NQT, HH, KSPLIT), 128, S_SMEM>>>(out);
}